// round 8
// baseline (speedup 1.0000x reference)
#include <cuda_runtime.h>

#define BB 2
#define LL 1024
#define DD 64
#define NROWS (BB*LL)
#define SCALE 0.35355339059327373f
#define LOG2E 1.4426950408889634f
#define SCALE2 (SCALE * LOG2E)

// persistent activations (no allocation allowed)
__device__ float g_qvs[NROWS*DD];
__device__ float g_kvs[NROWS*DD];
__device__ float g_attq[NROWS*DD];
__device__ float g_attk[NROWS*DD];
__device__ float g_q1[NROWS*DD];
__device__ float g_q2[NROWS*DD];
__device__ float g_kk[NROWS*DD];
__device__ float g_vv[NROWS*DD];

// piecewise-linear distance-bias tables (per block), pre-scaled by log2(e)
__device__ float g_pl_t[6][16];       // sorted breakpoints
__device__ float g_pl_AC[6][17][16];  // per interval: A[8], C[8] (C includes b2)
__device__ int   g_pl_i0[6];          // #{t_i <= 0}: search starts here (16 => skip)

__device__ __forceinline__ float ex2f(float x) {
    float r; asm("ex2.approx.f32 %0, %1;" : "=f"(r) : "f"(x)); return r;
}

// ---------------------------------------------------------------------------
// Setup: fold dist-bias MLP (1->16 relu ->8) into 17-interval piecewise-linear
// form, pre-scaled by log2(e) so scores feed ex2 directly.
// ---------------------------------------------------------------------------
__global__ void bias_setup_kernel(
    const float* __restrict__ bw1, const float* __restrict__ bb1,
    const float* __restrict__ bw2, const float* __restrict__ bb2)
{
    int i = blockIdx.x;
    if (threadIdx.x != 0) return;
    float w1[16], b1[16], t[16];
    for (int j = 0; j < 16; ++j) {
        w1[j] = bw1[i*16 + j];
        b1[j] = bb1[i*16 + j];
        t[j]  = (w1[j] != 0.f) ? (-b1[j] / w1[j]) : -1e30f;
    }
    int ord[16];
    for (int j = 0; j < 16; ++j) ord[j] = j;
    for (int a = 1; a < 16; ++a) {          // insertion sort by t
        int o = ord[a]; float tv = t[o]; int b = a - 1;
        while (b >= 0 && t[ord[b]] > tv) { ord[b+1] = ord[b]; --b; }
        ord[b+1] = o;
    }
    int i0 = 0;
    for (int j = 0; j < 16; ++j) {
        g_pl_t[i][j] = t[ord[j]];
        if (t[ord[j]] <= 0.f) ++i0;
    }
    g_pl_i0[i] = i0;                        // dist >= 0 => first i0 always passed
    for (int m = 0; m <= 16; ++m) {
        float A[8], C[8];
        for (int h = 0; h < 8; ++h) { A[h] = 0.f; C[h] = 0.f; }
        for (int a = 0; a < 16; ++a) {
            int j = ord[a];
            bool act;
            if (w1[j] > 0.f)      act = (a < m);
            else if (w1[j] < 0.f) act = (a >= m);
            else                  act = (b1[j] > 0.f);
            if (act) {
                for (int h = 0; h < 8; ++h) {
                    A[h] += w1[j] * bw2[i*128 + j*8 + h];
                    C[h] += b1[j] * bw2[i*128 + j*8 + h];
                }
            }
        }
        for (int h = 0; h < 8; ++h) {
            g_pl_AC[i][m][h]     = A[h] * LOG2E;
            g_pl_AC[i][m][8 + h] = (C[h] + bb2[i*8 + h]) * LOG2E;
        }
    }
}

// ---------------------------------------------------------------------------
// Embed: row-wise MLP concat(obs,s,f)[7] -> 256 -> 64
// ---------------------------------------------------------------------------
__global__ __launch_bounds__(256) void embed_kernel(
    const float* __restrict__ s_ctx, const float* __restrict__ f_ctx,
    const float* __restrict__ s_test, const float* __restrict__ table,
    const float* __restrict__ w1, const float* __restrict__ b1,
    const float* __restrict__ w2, const float* __restrict__ b2)
{
    __shared__ float xs[8];
    __shared__ float h[256];
    __shared__ float part[256];
    int row = blockIdx.x, tid = threadIdx.x;
    int sideq = row >> 11;
    int r = row & 2047;
    int b = r >> 10, pos = r & 1023;
    if (tid < 7) {
        float v;
        if (sideq == 0) {
            v = (tid < 4) ? table[4 + tid]
              : (tid < 6) ? s_ctx[(b*LL + pos)*2 + tid - 4]
                          : f_ctx[b*LL + pos];
        } else {
            v = (tid < 4) ? table[tid]
              : (tid < 6) ? s_test[(b*LL + pos)*2 + tid - 4]
                          : 0.f;
        }
        xs[tid] = v;
    }
    __syncthreads();
    float acc = b1[tid];
#pragma unroll
    for (int i = 0; i < 7; ++i) acc = fmaf(xs[i], w1[i*256 + tid], acc);
    h[tid] = fmaxf(acc, 0.f);
    __syncthreads();
    int o = tid & 63, half = tid >> 6;
    float p = 0.f;
#pragma unroll 8
    for (int j = half*64; j < half*64 + 64; ++j) p = fmaf(h[j], w2[j*64 + o], p);
    part[tid] = p;
    __syncthreads();
    if (tid < 64) {
        float v = part[tid] + part[tid+64] + part[tid+128] + part[tid+192] + b2[tid];
        float* dst = sideq ? g_qvs : g_kvs;
        dst[(b*LL + pos)*64 + tid] = v;
    }
}

// ---------------------------------------------------------------------------
// Projections (block 0 only)
// ---------------------------------------------------------------------------
__global__ __launch_bounds__(256) void proj_kernel(
    int iblk,
    const float* __restrict__ wq, const float* __restrict__ bq,
    const float* __restrict__ wk, const float* __restrict__ bk,
    const float* __restrict__ wv, const float* __restrict__ bv)
{
    __shared__ float sW[64*64];
    __shared__ float sX[32*64];
    int tid = threadIdx.x;
    int mat = blockIdx.y;
    const float *X, *W, *bias; float* dst;
    if (mat == 0)      { X = g_qvs; W = wq + iblk*4096; bias = bq + iblk*64; dst = g_q1; }
    else if (mat == 1) { X = g_kvs; W = wq + iblk*4096; bias = bq + iblk*64; dst = g_q2; }
    else if (mat == 2) { X = g_kvs; W = wk + iblk*4096; bias = bk + iblk*64; dst = g_kk; }
    else               { X = g_kvs; W = wv + iblk*4096; bias = bv + iblk*64; dst = g_vv; }
    int row0 = blockIdx.x * 32;
    for (int n = tid; n < 4096; n += 256) sW[n] = W[n];
    for (int n = tid; n < 2048; n += 256) sX[n] = X[row0*64 + n];
    __syncthreads();
    int r = tid >> 3, c0 = (tid & 7) * 8;
    float acc[8];
#pragma unroll
    for (int i = 0; i < 8; ++i) acc[i] = bias[c0 + i];
#pragma unroll 16
    for (int k = 0; k < 64; ++k) {
        float a = sX[r*64 + k];
#pragma unroll
        for (int i = 0; i < 8; ++i) acc[i] = fmaf(a, sW[k*64 + c0 + i], acc[i]);
    }
#pragma unroll
    for (int i = 0; i < 8; ++i) dst[(row0 + r)*64 + c0 + i] = acc[i];
}

// ---------------------------------------------------------------------------
// Fused biased attention + out-proj + residual + LN.
// grid (256, B, 2). CTA = 8 warps = 4 queries. Each warp: 2 queries x 2 heads
// (p = wid>>2 selects query pair, hq = wid&3 selects head pair) — every K/V
// LDS.128 feeds 4x FMAs (2 queries x 2 keys). PL bias with search skipped
// when all breakpoints <= 0 (true for this model: bias_b1 == 0). exp via ex2
// with log2e pre-folded into Q scale and A/C tables.
// ---------------------------------------------------------------------------
__global__ __launch_bounds__(256, 2) void attn_kernel(
    int iblk,
    const float* __restrict__ s_test, const float* __restrict__ s_ctx,
    const float* __restrict__ wo, const float* __restrict__ bo,
    const float* __restrict__ ns, const float* __restrict__ nb)
{
    __shared__ float4 sKf4[1024];   // 64 keys x 16 float4, XOR swizzled
    __shared__ float4 sVf4[1024];
    __shared__ float  sQ[256];      // 4 queries x 64, pre-scaled by SCALE*log2e
    __shared__ float2 sSk[64];
    __shared__ float2 sAC2[136];    // 17 intervals x 16 floats
    __shared__ float  sO[256];
    __shared__ float  sRed[4][2][2];

    const int tid = threadIdx.x, wid = tid >> 5, lane = tid & 31;
    const int side = blockIdx.z, b = blockIdx.y;
    const int p  = wid >> 2;        // query pair (queries 2p, 2p+1 of the CTA)
    const int hq = wid & 3;         // head pair (global heads 2hq, 2hq+1)
    const int qrow0 = b*LL + blockIdx.x*4 + 2*p;
    const int qrow1 = qrow0 + 1;

    const float* Qp  = side ? g_q2 : g_q1;
    const float* sqc = side ? s_ctx : s_test;

    for (int n = tid; n < 272; n += 256)
        ((float*)sAC2)[n] = ((const float*)g_pl_AC)[iblk*272 + n];
    sQ[tid] = Qp[(b*LL + blockIdx.x*4)*64 + tid] * SCALE2;

    const int i0 = g_pl_i0[iblk];
    const float* trg = g_pl_t[iblk];
    const float q0x = sqc[qrow0*2], q0y = sqc[qrow0*2 + 1];
    const float q1x = sqc[qrow1*2], q1y = sqc[qrow1*2 + 1];

    float l[4] = {0.f, 0.f, 0.f, 0.f};   // [q*2+h]
    float o[32];                          // [q*16 + h*8 + d]
#pragma unroll
    for (int d = 0; d < 32; ++d) o[d] = 0.f;

    const int ksw = lane & 15, kb0 = lane << 4;
    int ikk[4];
#pragma unroll
    for (int cc = 0; cc < 4; ++cc) ikk[cc] = kb0 + ((4*hq + cc) ^ ksw);
    const float4* sQw = ((const float4*)sQ) + p*32 + 4*hq;
    const float4* Kg = (const float4*)(g_kk + b*LL*64);
    const float4* Vg = (const float4*)(g_vv + b*LL*64);
    const float2* Skg = (const float2*)s_ctx + b*LL;

    for (int t = 0; t < 16; ++t) {
        __syncthreads();
#pragma unroll
        for (int n4 = 0; n4 < 4; ++n4) {
            int n = n4*256 + tid;
            int kr = n >> 4, c = n & 15;
            int sw = (kr << 4) + (c ^ (kr & 15));
            sKf4[sw] = Kg[t*1024 + n];
            sVf4[sw] = Vg[t*1024 + n];
        }
        if (tid < 64) sSk[tid] = Skg[t*64 + tid];
        __syncthreads();

        // 4 distances: 2 queries x 2 keys (keys lane, lane+32)
        float2 ck0 = sSk[lane], ck1 = sSk[lane + 32];
        float dx, dy;
        dx = q0x - ck0.x; dy = q0y - ck0.y; float d00 = fmaf(dx, dx, dy*dy);
        dx = q0x - ck1.x; dy = q0y - ck1.y; float d01 = fmaf(dx, dx, dy*dy);
        dx = q1x - ck0.x; dy = q1y - ck0.y; float d10 = fmaf(dx, dx, dy*dy);
        dx = q1x - ck1.x; dy = q1y - ck1.y; float d11 = fmaf(dx, dx, dy*dy);

        // interval index (loop empty when i0 == 16 — the real-data case)
        int m00 = i0, m01 = i0, m10 = i0, m11 = i0;
        for (int i = i0; i < 16; ++i) {
            float tv = trg[i];
            m00 += d00 > tv; m01 += d01 > tv;
            m10 += d10 > tv; m11 += d11 > tv;
        }

        float2 Aa = sAC2[m00*8 + hq], Ca = sAC2[m00*8 + 4 + hq];
        float2 Ab = sAC2[m01*8 + hq], Cb = sAC2[m01*8 + 4 + hq];
        float2 Ac = sAC2[m10*8 + hq], Cc = sAC2[m10*8 + 4 + hq];
        float2 Ad = sAC2[m11*8 + hq], Cd = sAC2[m11*8 + 4 + hq];

        // s[q*4 + k*2 + h]
        float s[8];
        s[0] = fmaf(Aa.x, d00, Ca.x);  s[1] = fmaf(Aa.y, d00, Ca.y);
        s[2] = fmaf(Ab.x, d01, Cb.x);  s[3] = fmaf(Ab.y, d01, Cb.y);
        s[4] = fmaf(Ac.x, d10, Cc.x);  s[5] = fmaf(Ac.y, d10, Cc.y);
        s[6] = fmaf(Ad.x, d11, Cd.x);  s[7] = fmaf(Ad.y, d11, Cd.y);

        // QK dots: each K load feeds both queries
#pragma unroll
        for (int cc = 0; cc < 4; ++cc) {
            const int h = cc >> 1;
            float4 k0 = sKf4[ikk[cc]];
            float4 k1 = sKf4[ikk[cc] + 512];
            float4 qa = sQw[cc];
            float4 qb = sQw[16 + cc];
            s[h]   = fmaf(qa.x,k0.x,s[h]);   s[h]   = fmaf(qa.y,k0.y,s[h]);
            s[h]   = fmaf(qa.z,k0.z,s[h]);   s[h]   = fmaf(qa.w,k0.w,s[h]);
            s[2+h] = fmaf(qa.x,k1.x,s[2+h]); s[2+h] = fmaf(qa.y,k1.y,s[2+h]);
            s[2+h] = fmaf(qa.z,k1.z,s[2+h]); s[2+h] = fmaf(qa.w,k1.w,s[2+h]);
            s[4+h] = fmaf(qb.x,k0.x,s[4+h]); s[4+h] = fmaf(qb.y,k0.y,s[4+h]);
            s[4+h] = fmaf(qb.z,k0.z,s[4+h]); s[4+h] = fmaf(qb.w,k0.w,s[4+h]);
            s[6+h] = fmaf(qb.x,k1.x,s[6+h]); s[6+h] = fmaf(qb.y,k1.y,s[6+h]);
            s[6+h] = fmaf(qb.z,k1.z,s[6+h]); s[6+h] = fmaf(qb.w,k1.w,s[6+h]);
        }

        float pr[8];
#pragma unroll
        for (int i = 0; i < 8; ++i) pr[i] = ex2f(s[i]);
        l[0] += pr[0] + pr[2];
        l[1] += pr[1] + pr[3];
        l[2] += pr[4] + pr[6];
        l[3] += pr[5] + pr[7];

        // V accumulation: each V load feeds both queries
#pragma unroll
        for (int cc = 0; cc < 4; ++cc) {
            const int h = cc >> 1, d0 = (cc & 1) * 4;
            float4 v0 = sVf4[ikk[cc]];
            float4 v1 = sVf4[ikk[cc] + 512];
            o[h*8+d0+0] = fmaf(pr[h],   v0.x, o[h*8+d0+0]);
            o[h*8+d0+0] = fmaf(pr[2+h], v1.x, o[h*8+d0+0]);
            o[h*8+d0+1] = fmaf(pr[h],   v0.y, o[h*8+d0+1]);
            o[h*8+d0+1] = fmaf(pr[2+h], v1.y, o[h*8+d0+1]);
            o[h*8+d0+2] = fmaf(pr[h],   v0.z, o[h*8+d0+2]);
            o[h*8+d0+2] = fmaf(pr[2+h], v1.z, o[h*8+d0+2]);
            o[h*8+d0+3] = fmaf(pr[h],   v0.w, o[h*8+d0+3]);
            o[h*8+d0+3] = fmaf(pr[2+h], v1.w, o[h*8+d0+3]);
            o[16+h*8+d0+0] = fmaf(pr[4+h], v0.x, o[16+h*8+d0+0]);
            o[16+h*8+d0+0] = fmaf(pr[6+h], v1.x, o[16+h*8+d0+0]);
            o[16+h*8+d0+1] = fmaf(pr[4+h], v0.y, o[16+h*8+d0+1]);
            o[16+h*8+d0+1] = fmaf(pr[6+h], v1.y, o[16+h*8+d0+1]);
            o[16+h*8+d0+2] = fmaf(pr[4+h], v0.z, o[16+h*8+d0+2]);
            o[16+h*8+d0+2] = fmaf(pr[6+h], v1.z, o[16+h*8+d0+2]);
            o[16+h*8+d0+3] = fmaf(pr[4+h], v0.w, o[16+h*8+d0+3]);
            o[16+h*8+d0+3] = fmaf(pr[6+h], v1.w, o[16+h*8+d0+3]);
        }
    }

    // merge lanes (butterfly)
#pragma unroll
    for (int i = 0; i < 4; ++i) {
        float lh = l[i];
#pragma unroll
        for (int off = 16; off; off >>= 1)
            lh += __shfl_xor_sync(0xffffffffu, lh, off);
        l[i] = lh;
    }
#pragma unroll
    for (int d = 0; d < 32; ++d) {
        float v = o[d];
#pragma unroll
        for (int off = 16; off; off >>= 1)
            v += __shfl_xor_sync(0xffffffffu, v, off);
        o[d] = v;
    }
    float inv[4];
#pragma unroll
    for (int i = 0; i < 4; ++i) inv[i] = 1.f / l[i];
#pragma unroll
    for (int d = 0; d < 32; ++d) o[d] *= inv[(d >> 4)*2 + ((d >> 3) & 1)];

    // lane extraction: lane holds o[lane]
    float myv = 0.f;
#pragma unroll
    for (int i = 0; i < 32; ++i)
        if (lane == i) myv = o[i];

    __syncthreads();   // all warps done with sK/sV
    sO[(2*p + (lane >> 4))*64 + 16*hq + (lane & 15)] = myv;
    float* sWo = (float*)sKf4;
    const float* Wog = wo + iblk*4096;
    for (int n = tid; n < 4096; n += 256) sWo[n] = Wog[n];
    __syncthreads();

    // out-proj + residual + LN: thread (qc = tid>>6, c = tid&63)
    const int qc = tid >> 6, c = tid & 63;
    const int qrow_e = b*LL + blockIdx.x*4 + qc;
    float acc = bo[iblk*64 + c];
#pragma unroll 16
    for (int i = 0; i < 64; ++i)
        acc = fmaf(sO[qc*64 + i], sWo[i*64 + c], acc);
    const float* src = side ? g_kvs : g_qvs;
    acc += src[qrow_e*64 + c];

    float s1 = acc, s2 = acc*acc;
#pragma unroll
    for (int off = 16; off; off >>= 1) {
        s1 += __shfl_xor_sync(0xffffffffu, s1, off);
        s2 += __shfl_xor_sync(0xffffffffu, s2, off);
    }
    const int half = (tid >> 5) & 1;
    if (lane == 0) { sRed[qc][half][0] = s1; sRed[qc][half][1] = s2; }
    __syncthreads();
    float tot  = sRed[qc][0][0] + sRed[qc][1][0];
    float tot2 = sRed[qc][0][1] + sRed[qc][1][1];
    float mu = tot * (1.f/64.f);
    float var = tot2 * (1.f/64.f) - mu*mu;
    float rstd = rsqrtf(var + 1e-6f);

    float* outp = side ? g_attk : g_attq;
    outp[qrow_e*64 + c] = (acc - mu) * rstd * ns[iblk*64 + c] + nb[iblk*64 + c];
}

// ---------------------------------------------------------------------------
// FFN (64->128 relu ->64) + residual + LN + NEXT-BLOCK projections.
// ---------------------------------------------------------------------------
__global__ __launch_bounds__(128) void ffnproj_kernel(
    int iblk, int nblk,
    const float* __restrict__ fw1, const float* __restrict__ fb1,
    const float* __restrict__ fw2, const float* __restrict__ fb2,
    const float* __restrict__ ns, const float* __restrict__ nb,
    const float* __restrict__ wq, const float* __restrict__ bq,
    const float* __restrict__ wk, const float* __restrict__ bk,
    const float* __restrict__ wv, const float* __restrict__ bv)
{
    __shared__ float sx[8][64];
    __shared__ float sh[8][128];
    __shared__ float sy[8][64];
    __shared__ float sred[8][2][2];

    int tid = threadIdx.x;
    int row0 = blockIdx.x * 8;
    int side = row0 >> 11;
    int r0 = row0 & 2047;
    const float* src = side ? g_attk : g_attq;
    float* dst = side ? g_kvs : g_qvs;

    for (int n = tid; n < 512; n += 128) sx[n >> 6][n & 63] = src[r0*64 + n];
    __syncthreads();

    const float* W1 = fw1 + iblk*8192;
    float b1v = fb1[iblk*128 + tid];
    float acc[8];
#pragma unroll
    for (int r = 0; r < 8; ++r) acc[r] = b1v;
#pragma unroll 8
    for (int k = 0; k < 64; ++k) {
        float w = W1[k*128 + tid];
#pragma unroll
        for (int r = 0; r < 8; ++r) acc[r] = fmaf(sx[r][k], w, acc[r]);
    }
#pragma unroll
    for (int r = 0; r < 8; ++r) sh[r][tid] = fmaxf(acc[r], 0.f);
    __syncthreads();

    const float* W2 = fw2 + iblk*8192;
    int c = tid & 63, g = tid >> 6;
    float b2v = fb2[iblk*64 + c];
    float a2[4];
#pragma unroll
    for (int r = 0; r < 4; ++r) a2[r] = b2v;
#pragma unroll 8
    for (int k = 0; k < 128; ++k) {
        float w = W2[k*64 + c];
#pragma unroll
        for (int r = 0; r < 4; ++r) a2[r] = fmaf(sh[g*4 + r][k], w, a2[r]);
    }
#pragma unroll
    for (int r = 0; r < 4; ++r) a2[r] += sx[g*4 + r][c];

    float s1[4], s2[4];
#pragma unroll
    for (int r = 0; r < 4; ++r) { s1[r] = a2[r]; s2[r] = a2[r]*a2[r]; }
#pragma unroll
    for (int off = 16; off; off >>= 1) {
#pragma unroll
        for (int r = 0; r < 4; ++r) {
            s1[r] += __shfl_xor_sync(0xffffffffu, s1[r], off);
            s2[r] += __shfl_xor_sync(0xffffffffu, s2[r], off);
        }
    }
    int lane = tid & 31, half = (tid >> 5) & 1;
    if (lane == 0) {
#pragma unroll
        for (int r = 0; r < 4; ++r) {
            sred[g*4 + r][half][0] = s1[r];
            sred[g*4 + r][half][1] = s2[r];
        }
    }
    __syncthreads();
    float nsv = ns[iblk*64 + c], nbv = nb[iblk*64 + c];
#pragma unroll
    for (int r = 0; r < 4; ++r) {
        int rr = g*4 + r;
        float tot  = sred[rr][0][0] + sred[rr][1][0];
        float tot2 = sred[rr][0][1] + sred[rr][1][1];
        float mu = tot * (1.f/64.f);
        float var = tot2 * (1.f/64.f) - mu*mu;
        float rstd = rsqrtf(var + 1e-6f);
        float y = (a2[r] - mu) * rstd * nsv + nbv;
        sy[rr][c] = y;
        dst[(r0 + rr)*64 + c] = y;
    }
    __syncthreads();

    if (nblk < 0) return;

    const float* Wm[3]; const float* Bm[3]; float* Dm[3]; int nmat;
    if (side == 0) {
        nmat = 1;
        Wm[0] = wq + nblk*4096; Bm[0] = bq + nblk*64; Dm[0] = g_q1;
    } else {
        nmat = 3;
        Wm[0] = wq + nblk*4096; Bm[0] = bq + nblk*64; Dm[0] = g_q2;
        Wm[1] = wk + nblk*4096; Bm[1] = bk + nblk*64; Dm[1] = g_kk;
        Wm[2] = wv + nblk*4096; Bm[2] = bv + nblk*64; Dm[2] = g_vv;
    }
    for (int mm = 0; mm < nmat; ++mm) {
        const float* W = Wm[mm];
        float bv = Bm[mm][c];
        float pa[4];
#pragma unroll
        for (int r = 0; r < 4; ++r) pa[r] = bv;
#pragma unroll 8
        for (int k = 0; k < 64; ++k) {
            float w = W[k*64 + c];
#pragma unroll
            for (int r = 0; r < 4; ++r) pa[r] = fmaf(sy[g*4 + r][k], w, pa[r]);
        }
#pragma unroll
        for (int r = 0; r < 4; ++r) Dm[mm][(r0 + g*4 + r)*64 + c] = pa[r];
    }
}

// ---------------------------------------------------------------------------
// Head: final LN + MLP 64->128 relu ->2.  out = [mu(2048) | std(2048)]
// ---------------------------------------------------------------------------
__global__ __launch_bounds__(128) void head_kernel(
    const float* __restrict__ fns, const float* __restrict__ fnb,
    const float* __restrict__ hw1, const float* __restrict__ hb1,
    const float* __restrict__ hw2, const float* __restrict__ hb2,
    float* __restrict__ out)
{
    __shared__ float sx[64], sh[128], sp0[128], sp1[128], sred[2];
    int row = blockIdx.x, tid = threadIdx.x;
    if (tid < 64) sx[tid] = g_qvs[row*64 + tid];
    __syncthreads();
    if (tid < 32) {
        float v0 = sx[tid], v1 = sx[tid + 32];
        float s = v0 + v1;
#pragma unroll
        for (int off = 16; off; off >>= 1)
            s += __shfl_xor_sync(0xffffffffu, s, off);
        float mu = s * (1.f/64.f);
        float e0 = v0 - mu, e1 = v1 - mu;
        float qv = fmaf(e0, e0, e1*e1);
#pragma unroll
        for (int off = 16; off; off >>= 1)
            qv += __shfl_xor_sync(0xffffffffu, qv, off);
        if (tid == 0) { sred[0] = mu; sred[1] = rsqrtf(qv*(1.f/64.f) + 1e-6f); }
    }
    __syncthreads();
    if (tid < 64) sx[tid] = (sx[tid] - sred[0]) * sred[1] * fns[tid] + fnb[tid];
    __syncthreads();
    float acc = hb1[tid];
#pragma unroll 16
    for (int k = 0; k < 64; ++k) acc = fmaf(sx[k], hw1[k*128 + tid], acc);
    sh[tid] = fmaxf(acc, 0.f);
    __syncthreads();
    sp0[tid] = sh[tid] * hw2[tid*2 + 0];
    sp1[tid] = sh[tid] * hw2[tid*2 + 1];
    __syncthreads();
    for (int s = 64; s > 0; s >>= 1) {
        if (tid < s) { sp0[tid] += sp0[tid + s]; sp1[tid] += sp1[tid + s]; }
        __syncthreads();
    }
    if (tid == 0) {
        out[row]        = sp0[0] + hb2[0];
        out[2048 + row] = __expf(0.5f * (sp1[0] + hb2[1]));
    }
}

// ---------------------------------------------------------------------------
extern "C" void kernel_launch(void* const* d_in, const int* in_sizes, int n_in,
                              void* d_out, int out_size)
{
    const float* s_ctx   = (const float*)d_in[0];
    const float* f_ctx   = (const float*)d_in[1];
    const float* s_test  = (const float*)d_in[2];
    const float* table   = (const float*)d_in[3];
    const float* emb_w1  = (const float*)d_in[4];
    const float* emb_b1  = (const float*)d_in[5];
    const float* emb_w2  = (const float*)d_in[6];
    const float* emb_b2  = (const float*)d_in[7];
    const float* attn_wq = (const float*)d_in[8];
    const float* attn_bq = (const float*)d_in[9];
    const float* attn_wk = (const float*)d_in[10];
    const float* attn_bk = (const float*)d_in[11];
    const float* attn_wv = (const float*)d_in[12];
    const float* attn_bv = (const float*)d_in[13];
    const float* attn_wo = (const float*)d_in[14];
    const float* attn_bo = (const float*)d_in[15];
    const float* ffn_w1  = (const float*)d_in[16];
    const float* ffn_b1  = (const float*)d_in[17];
    const float* ffn_w2  = (const float*)d_in[18];
    const float* ffn_b2  = (const float*)d_in[19];
    const float* bias_w1 = (const float*)d_in[20];
    const float* bias_b1 = (const float*)d_in[21];
    const float* bias_w2 = (const float*)d_in[22];
    const float* bias_b2 = (const float*)d_in[23];
    const float* norm_s  = (const float*)d_in[24];
    const float* norm_b  = (const float*)d_in[25];
    const float* fnorm_s = (const float*)d_in[26];
    const float* fnorm_b = (const float*)d_in[27];
    const float* head_w1 = (const float*)d_in[28];
    const float* head_b1 = (const float*)d_in[29];
    const float* head_w2 = (const float*)d_in[30];
    const float* head_b2 = (const float*)d_in[31];

    bias_setup_kernel<<<6, 32>>>(bias_w1, bias_b1, bias_w2, bias_b2);
    embed_kernel<<<4096, 256>>>(s_ctx, f_ctx, s_test, table,
                                emb_w1, emb_b1, emb_w2, emb_b2);
    proj_kernel<<<dim3(64, 4), 256>>>(0, attn_wq, attn_bq,
                                      attn_wk, attn_bk, attn_wv, attn_bv);
    for (int i = 0; i < 6; ++i) {
        attn_kernel<<<dim3(256, BB, 2), 256>>>(i, s_test, s_ctx,
                                               attn_wo, attn_bo, norm_s, norm_b);
        ffnproj_kernel<<<512, 128>>>(i, (i < 5) ? i + 1 : -1,
                                     ffn_w1, ffn_b1, ffn_w2, ffn_b2,
                                     norm_s, norm_b,
                                     attn_wq, attn_bq, attn_wk, attn_bk,
                                     attn_wv, attn_bv);
    }
    head_kernel<<<2048, 128>>>(fnorm_s, fnorm_b, head_w1, head_b1,
                               head_w2, head_b2, (float*)d_out);
}

// round 9
// speedup vs baseline: 1.1999x; 1.1999x over previous
#include <cuda_runtime.h>

#define BB 2
#define LL 1024
#define DD 64
#define NROWS (BB*LL)
#define SCALE 0.35355339059327373f
#define LOG2E 1.4426950408889634f
#define SCALE2 (SCALE * LOG2E)

// persistent activations (no allocation allowed)
__device__ float g_qvs[NROWS*DD];
__device__ float g_kvs[NROWS*DD];
__device__ float g_attq[NROWS*DD];
__device__ float g_attk[NROWS*DD];
__device__ float g_q1[NROWS*DD];
__device__ float g_q2[NROWS*DD];
__device__ float g_kk[NROWS*DD];
__device__ float g_vv[NROWS*DD];

// piecewise-linear distance-bias tables (per block), pre-scaled by log2(e)
__device__ float g_pl_t[6][16];
__device__ float g_pl_AC[6][17][16];
__device__ int   g_pl_i0[6];

__device__ __forceinline__ float ex2f(float x) {
    float r; asm("ex2.approx.f32 %0, %1;" : "=f"(r) : "f"(x)); return r;
}
__device__ __forceinline__ unsigned smem_u32(const void* p) {
    return (unsigned)__cvta_generic_to_shared(p);
}
__device__ __forceinline__ void cpa16(unsigned dst, const void* src) {
    asm volatile("cp.async.cg.shared.global [%0], [%1], 16;" :: "r"(dst), "l"(src));
}
__device__ __forceinline__ void cpa8(unsigned dst, const void* src) {
    asm volatile("cp.async.ca.shared.global [%0], [%1], 8;" :: "r"(dst), "l"(src));
}

// ---------------------------------------------------------------------------
// Setup: fold dist-bias MLP into 17-interval piecewise-linear form (x log2e).
// ---------------------------------------------------------------------------
__global__ void bias_setup_kernel(
    const float* __restrict__ bw1, const float* __restrict__ bb1,
    const float* __restrict__ bw2, const float* __restrict__ bb2)
{
    int i = blockIdx.x;
    if (threadIdx.x != 0) return;
    float w1[16], b1[16], t[16];
    for (int j = 0; j < 16; ++j) {
        w1[j] = bw1[i*16 + j];
        b1[j] = bb1[i*16 + j];
        t[j]  = (w1[j] != 0.f) ? (-b1[j] / w1[j]) : -1e30f;
    }
    int ord[16];
    for (int j = 0; j < 16; ++j) ord[j] = j;
    for (int a = 1; a < 16; ++a) {
        int o = ord[a]; float tv = t[o]; int b = a - 1;
        while (b >= 0 && t[ord[b]] > tv) { ord[b+1] = ord[b]; --b; }
        ord[b+1] = o;
    }
    int i0 = 0;
    for (int j = 0; j < 16; ++j) {
        g_pl_t[i][j] = t[ord[j]];
        if (t[ord[j]] <= 0.f) ++i0;
    }
    g_pl_i0[i] = i0;
    for (int m = 0; m <= 16; ++m) {
        float A[8], C[8];
        for (int h = 0; h < 8; ++h) { A[h] = 0.f; C[h] = 0.f; }
        for (int a = 0; a < 16; ++a) {
            int j = ord[a];
            bool act;
            if (w1[j] > 0.f)      act = (a < m);
            else if (w1[j] < 0.f) act = (a >= m);
            else                  act = (b1[j] > 0.f);
            if (act) {
                for (int h = 0; h < 8; ++h) {
                    A[h] += w1[j] * bw2[i*128 + j*8 + h];
                    C[h] += b1[j] * bw2[i*128 + j*8 + h];
                }
            }
        }
        for (int h = 0; h < 8; ++h) {
            g_pl_AC[i][m][h]     = A[h] * LOG2E;
            g_pl_AC[i][m][8 + h] = (C[h] + bb2[i*8 + h]) * LOG2E;
        }
    }
}

// ---------------------------------------------------------------------------
// Embed
// ---------------------------------------------------------------------------
__global__ __launch_bounds__(256) void embed_kernel(
    const float* __restrict__ s_ctx, const float* __restrict__ f_ctx,
    const float* __restrict__ s_test, const float* __restrict__ table,
    const float* __restrict__ w1, const float* __restrict__ b1,
    const float* __restrict__ w2, const float* __restrict__ b2)
{
    __shared__ float xs[8];
    __shared__ float h[256];
    __shared__ float part[256];
    int row = blockIdx.x, tid = threadIdx.x;
    int sideq = row >> 11;
    int r = row & 2047;
    int b = r >> 10, pos = r & 1023;
    if (tid < 7) {
        float v;
        if (sideq == 0) {
            v = (tid < 4) ? table[4 + tid]
              : (tid < 6) ? s_ctx[(b*LL + pos)*2 + tid - 4]
                          : f_ctx[b*LL + pos];
        } else {
            v = (tid < 4) ? table[tid]
              : (tid < 6) ? s_test[(b*LL + pos)*2 + tid - 4]
                          : 0.f;
        }
        xs[tid] = v;
    }
    __syncthreads();
    float acc = b1[tid];
#pragma unroll
    for (int i = 0; i < 7; ++i) acc = fmaf(xs[i], w1[i*256 + tid], acc);
    h[tid] = fmaxf(acc, 0.f);
    __syncthreads();
    int o = tid & 63, half = tid >> 6;
    float p = 0.f;
#pragma unroll 8
    for (int j = half*64; j < half*64 + 64; ++j) p = fmaf(h[j], w2[j*64 + o], p);
    part[tid] = p;
    __syncthreads();
    if (tid < 64) {
        float v = part[tid] + part[tid+64] + part[tid+128] + part[tid+192] + b2[tid];
        float* dst = sideq ? g_qvs : g_kvs;
        dst[(b*LL + pos)*64 + tid] = v;
    }
}

// ---------------------------------------------------------------------------
// Projections (block 0 only)
// ---------------------------------------------------------------------------
__global__ __launch_bounds__(256) void proj_kernel(
    int iblk,
    const float* __restrict__ wq, const float* __restrict__ bq,
    const float* __restrict__ wk, const float* __restrict__ bk,
    const float* __restrict__ wv, const float* __restrict__ bv)
{
    __shared__ float sW[64*64];
    __shared__ float sX[32*64];
    int tid = threadIdx.x;
    int mat = blockIdx.y;
    const float *X, *W, *bias; float* dst;
    if (mat == 0)      { X = g_qvs; W = wq + iblk*4096; bias = bq + iblk*64; dst = g_q1; }
    else if (mat == 1) { X = g_kvs; W = wq + iblk*4096; bias = bq + iblk*64; dst = g_q2; }
    else if (mat == 2) { X = g_kvs; W = wk + iblk*4096; bias = bk + iblk*64; dst = g_kk; }
    else               { X = g_kvs; W = wv + iblk*4096; bias = bv + iblk*64; dst = g_vv; }
    int row0 = blockIdx.x * 32;
    for (int n = tid; n < 4096; n += 256) sW[n] = W[n];
    for (int n = tid; n < 2048; n += 256) sX[n] = X[row0*64 + n];
    __syncthreads();
    int r = tid >> 3, c0 = (tid & 7) * 8;
    float acc[8];
#pragma unroll
    for (int i = 0; i < 8; ++i) acc[i] = bias[c0 + i];
#pragma unroll 16
    for (int k = 0; k < 64; ++k) {
        float a = sX[r*64 + k];
#pragma unroll
        for (int i = 0; i < 8; ++i) acc[i] = fmaf(a, sW[k*64 + c0 + i], acc[i]);
    }
#pragma unroll
    for (int i = 0; i < 8; ++i) dst[(row0 + r)*64 + c0 + i] = acc[i];
}

// ---------------------------------------------------------------------------
// Fused biased attention + out-proj + residual + LN.
// grid (256, B, 2). CTA = 8 warps = 4 queries, warp = 2 queries x 2 heads.
// cp.async double-buffered K/V tiles (dynamic smem 64KB), Q in registers.
// ---------------------------------------------------------------------------
__global__ __launch_bounds__(256, 2) void attn_kernel(
    int iblk,
    const float* __restrict__ s_test, const float* __restrict__ s_ctx,
    const float* __restrict__ wo, const float* __restrict__ bo,
    const float* __restrict__ ns, const float* __restrict__ nb)
{
    // dynamic: K0[1024] V0[1024] K1[1024] V1[1024] float4
    extern __shared__ float4 dyn[];
    float4* KB[2] = { dyn,        dyn + 2048 };
    float4* VB[2] = { dyn + 1024, dyn + 3072 };

    __shared__ float  sQ[256];
    __shared__ float2 sSk2[2][64];
    __shared__ float2 sAC2[136];
    __shared__ float  sO[256];
    __shared__ float  sRed[4][2][2];

    const int tid = threadIdx.x, wid = tid >> 5, lane = tid & 31;
    const int side = blockIdx.z, b = blockIdx.y;
    const int p  = wid >> 2;
    const int hq = wid & 3;
    const int qrow0 = b*LL + blockIdx.x*4 + 2*p;
    const int qrow1 = qrow0 + 1;

    const float* Qp  = side ? g_q2 : g_q1;
    const float* sqc = side ? s_ctx : s_test;

    for (int n = tid; n < 272; n += 256)
        ((float*)sAC2)[n] = ((const float*)g_pl_AC)[iblk*272 + n];
    sQ[tid] = Qp[(b*LL + blockIdx.x*4)*64 + tid] * SCALE2;

    const int i0 = g_pl_i0[iblk];
    const float* trg = g_pl_t[iblk];
    const float q0x = sqc[qrow0*2], q0y = sqc[qrow0*2 + 1];
    const float q1x = sqc[qrow1*2], q1y = sqc[qrow1*2 + 1];

    float l[4] = {0.f, 0.f, 0.f, 0.f};
    float o[32];
#pragma unroll
    for (int d = 0; d < 32; ++d) o[d] = 0.f;

    const int ksw = lane & 15, kb0 = lane << 4;
    int ikk[4];
#pragma unroll
    for (int cc = 0; cc < 4; ++cc) ikk[cc] = kb0 + ((4*hq + cc) ^ ksw);
    const float4* Kg = (const float4*)(g_kk + b*LL*64);
    const float4* Vg = (const float4*)(g_vv + b*LL*64);
    const float2* Skg = (const float2*)s_ctx + b*LL;

    // staging indices for this thread (4 float4 per buffer)
    int sgN[4], sgSw[4];
#pragma unroll
    for (int n4 = 0; n4 < 4; ++n4) {
        int n = n4*256 + tid;
        int kr = n >> 4, c = n & 15;
        sgN[n4]  = n;
        sgSw[n4] = (kr << 4) + (c ^ (kr & 15));
    }

    __syncthreads();   // sQ/sAC visible
    // hoist Q into registers
    float4 qa[4], qb[4];
    {
        const float4* sQw = ((const float4*)sQ) + p*32 + 4*hq;
#pragma unroll
        for (int cc = 0; cc < 4; ++cc) { qa[cc] = sQw[cc]; qb[cc] = sQw[16 + cc]; }
    }

    // prologue: stage tile 0 into buffer 0
#pragma unroll
    for (int n4 = 0; n4 < 4; ++n4) {
        cpa16(smem_u32(&KB[0][sgSw[n4]]), &Kg[sgN[n4]]);
        cpa16(smem_u32(&VB[0][sgSw[n4]]), &Vg[sgN[n4]]);
    }
    if (tid < 64) cpa8(smem_u32(&sSk2[0][tid]), &Skg[tid]);
    asm volatile("cp.async.commit_group;");

    for (int t = 0; t < 16; ++t) {
        const int bf = t & 1, nbf = bf ^ 1;
        if (t + 1 < 16) {
#pragma unroll
            for (int n4 = 0; n4 < 4; ++n4) {
                cpa16(smem_u32(&KB[nbf][sgSw[n4]]), &Kg[(t+1)*1024 + sgN[n4]]);
                cpa16(smem_u32(&VB[nbf][sgSw[n4]]), &Vg[(t+1)*1024 + sgN[n4]]);
            }
            if (tid < 64) cpa8(smem_u32(&sSk2[nbf][tid]), &Skg[(t+1)*64 + tid]);
            asm volatile("cp.async.commit_group;");
            asm volatile("cp.async.wait_group 1;");
        } else {
            asm volatile("cp.async.wait_group 0;");
        }
        __syncthreads();   // tile t data visible to all

        const float4* sK = KB[bf];
        const float4* sV = VB[bf];

        float2 ck0 = sSk2[bf][lane], ck1 = sSk2[bf][lane + 32];
        float dx, dy;
        dx = q0x - ck0.x; dy = q0y - ck0.y; float d00 = fmaf(dx, dx, dy*dy);
        dx = q0x - ck1.x; dy = q0y - ck1.y; float d01 = fmaf(dx, dx, dy*dy);
        dx = q1x - ck0.x; dy = q1y - ck0.y; float d10 = fmaf(dx, dx, dy*dy);
        dx = q1x - ck1.x; dy = q1y - ck1.y; float d11 = fmaf(dx, dx, dy*dy);

        int m00 = i0, m01 = i0, m10 = i0, m11 = i0;
        for (int i = i0; i < 16; ++i) {
            float tv = trg[i];
            m00 += d00 > tv; m01 += d01 > tv;
            m10 += d10 > tv; m11 += d11 > tv;
        }

        float2 Aa = sAC2[m00*8 + hq], Ca = sAC2[m00*8 + 4 + hq];
        float2 Ab = sAC2[m01*8 + hq], Cb = sAC2[m01*8 + 4 + hq];
        float2 Ac = sAC2[m10*8 + hq], Cc = sAC2[m10*8 + 4 + hq];
        float2 Ad = sAC2[m11*8 + hq], Cd = sAC2[m11*8 + 4 + hq];

        float s[8];
        s[0] = fmaf(Aa.x, d00, Ca.x);  s[1] = fmaf(Aa.y, d00, Ca.y);
        s[2] = fmaf(Ab.x, d01, Cb.x);  s[3] = fmaf(Ab.y, d01, Cb.y);
        s[4] = fmaf(Ac.x, d10, Cc.x);  s[5] = fmaf(Ac.y, d10, Cc.y);
        s[6] = fmaf(Ad.x, d11, Cd.x);  s[7] = fmaf(Ad.y, d11, Cd.y);

#pragma unroll
        for (int cc = 0; cc < 4; ++cc) {
            const int h = cc >> 1;
            float4 k0 = sK[ikk[cc]];
            float4 k1 = sK[ikk[cc] + 512];
            s[h]   = fmaf(qa[cc].x,k0.x,s[h]);   s[h]   = fmaf(qa[cc].y,k0.y,s[h]);
            s[h]   = fmaf(qa[cc].z,k0.z,s[h]);   s[h]   = fmaf(qa[cc].w,k0.w,s[h]);
            s[2+h] = fmaf(qa[cc].x,k1.x,s[2+h]); s[2+h] = fmaf(qa[cc].y,k1.y,s[2+h]);
            s[2+h] = fmaf(qa[cc].z,k1.z,s[2+h]); s[2+h] = fmaf(qa[cc].w,k1.w,s[2+h]);
            s[4+h] = fmaf(qb[cc].x,k0.x,s[4+h]); s[4+h] = fmaf(qb[cc].y,k0.y,s[4+h]);
            s[4+h] = fmaf(qb[cc].z,k0.z,s[4+h]); s[4+h] = fmaf(qb[cc].w,k0.w,s[4+h]);
            s[6+h] = fmaf(qb[cc].x,k1.x,s[6+h]); s[6+h] = fmaf(qb[cc].y,k1.y,s[6+h]);
            s[6+h] = fmaf(qb[cc].z,k1.z,s[6+h]); s[6+h] = fmaf(qb[cc].w,k1.w,s[6+h]);
        }

        float pr[8];
#pragma unroll
        for (int i = 0; i < 8; ++i) pr[i] = ex2f(s[i]);
        l[0] += pr[0] + pr[2];
        l[1] += pr[1] + pr[3];
        l[2] += pr[4] + pr[6];
        l[3] += pr[5] + pr[7];

#pragma unroll
        for (int cc = 0; cc < 4; ++cc) {
            const int h = cc >> 1, d0 = (cc & 1) * 4;
            float4 v0 = sV[ikk[cc]];
            float4 v1 = sV[ikk[cc] + 512];
            o[h*8+d0+0] = fmaf(pr[h],   v0.x, o[h*8+d0+0]);
            o[h*8+d0+0] = fmaf(pr[2+h], v1.x, o[h*8+d0+0]);
            o[h*8+d0+1] = fmaf(pr[h],   v0.y, o[h*8+d0+1]);
            o[h*8+d0+1] = fmaf(pr[2+h], v1.y, o[h*8+d0+1]);
            o[h*8+d0+2] = fmaf(pr[h],   v0.z, o[h*8+d0+2]);
            o[h*8+d0+2] = fmaf(pr[2+h], v1.z, o[h*8+d0+2]);
            o[h*8+d0+3] = fmaf(pr[h],   v0.w, o[h*8+d0+3]);
            o[h*8+d0+3] = fmaf(pr[2+h], v1.w, o[h*8+d0+3]);
            o[16+h*8+d0+0] = fmaf(pr[4+h], v0.x, o[16+h*8+d0+0]);
            o[16+h*8+d0+0] = fmaf(pr[6+h], v1.x, o[16+h*8+d0+0]);
            o[16+h*8+d0+1] = fmaf(pr[4+h], v0.y, o[16+h*8+d0+1]);
            o[16+h*8+d0+1] = fmaf(pr[6+h], v1.y, o[16+h*8+d0+1]);
            o[16+h*8+d0+2] = fmaf(pr[4+h], v0.z, o[16+h*8+d0+2]);
            o[16+h*8+d0+2] = fmaf(pr[6+h], v1.z, o[16+h*8+d0+2]);
            o[16+h*8+d0+3] = fmaf(pr[4+h], v0.w, o[16+h*8+d0+3]);
            o[16+h*8+d0+3] = fmaf(pr[6+h], v1.w, o[16+h*8+d0+3]);
        }
        __syncthreads();   // all done reading buf bf before it is re-staged
    }

    // merge lanes (butterfly)
#pragma unroll
    for (int i = 0; i < 4; ++i) {
        float lh = l[i];
#pragma unroll
        for (int off = 16; off; off >>= 1)
            lh += __shfl_xor_sync(0xffffffffu, lh, off);
        l[i] = lh;
    }
#pragma unroll
    for (int d = 0; d < 32; ++d) {
        float v = o[d];
#pragma unroll
        for (int off = 16; off; off >>= 1)
            v += __shfl_xor_sync(0xffffffffu, v, off);
        o[d] = v;
    }
    float inv[4];
#pragma unroll
    for (int i = 0; i < 4; ++i) inv[i] = 1.f / l[i];
#pragma unroll
    for (int d = 0; d < 32; ++d) o[d] *= inv[(d >> 4)*2 + ((d >> 3) & 1)];

    float myv = 0.f;
#pragma unroll
    for (int i = 0; i < 32; ++i)
        if (lane == i) myv = o[i];

    sO[(2*p + (lane >> 4))*64 + 16*hq + (lane & 15)] = myv;
    float* sWo = (float*)dyn;
    const float* Wog = wo + iblk*4096;
    for (int n = tid; n < 4096; n += 256) sWo[n] = Wog[n];
    __syncthreads();

    const int qc = tid >> 6, c = tid & 63;
    const int qrow_e = b*LL + blockIdx.x*4 + qc;
    float acc = bo[iblk*64 + c];
#pragma unroll 16
    for (int i = 0; i < 64; ++i)
        acc = fmaf(sO[qc*64 + i], sWo[i*64 + c], acc);
    const float* src = side ? g_kvs : g_qvs;
    acc += src[qrow_e*64 + c];

    float s1 = acc, s2 = acc*acc;
#pragma unroll
    for (int off = 16; off; off >>= 1) {
        s1 += __shfl_xor_sync(0xffffffffu, s1, off);
        s2 += __shfl_xor_sync(0xffffffffu, s2, off);
    }
    const int half = (tid >> 5) & 1;
    if (lane == 0) { sRed[qc][half][0] = s1; sRed[qc][half][1] = s2; }
    __syncthreads();
    float tot  = sRed[qc][0][0] + sRed[qc][1][0];
    float tot2 = sRed[qc][0][1] + sRed[qc][1][1];
    float mu = tot * (1.f/64.f);
    float var = tot2 * (1.f/64.f) - mu*mu;
    float rstd = rsqrtf(var + 1e-6f);

    float* outp = side ? g_attk : g_attq;
    outp[qrow_e*64 + c] = (acc - mu) * rstd * ns[iblk*64 + c] + nb[iblk*64 + c];
}

// ---------------------------------------------------------------------------
// FFN + residual + LN + next-block projections.
// ---------------------------------------------------------------------------
__global__ __launch_bounds__(128) void ffnproj_kernel(
    int iblk, int nblk,
    const float* __restrict__ fw1, const float* __restrict__ fb1,
    const float* __restrict__ fw2, const float* __restrict__ fb2,
    const float* __restrict__ ns, const float* __restrict__ nb,
    const float* __restrict__ wq, const float* __restrict__ bq,
    const float* __restrict__ wk, const float* __restrict__ bk,
    const float* __restrict__ wv, const float* __restrict__ bv)
{
    __shared__ float sx[8][64];
    __shared__ float sh[8][128];
    __shared__ float sy[8][64];
    __shared__ float sred[8][2][2];

    int tid = threadIdx.x;
    int row0 = blockIdx.x * 8;
    int side = row0 >> 11;
    int r0 = row0 & 2047;
    const float* src = side ? g_attk : g_attq;
    float* dst = side ? g_kvs : g_qvs;

    for (int n = tid; n < 512; n += 128) sx[n >> 6][n & 63] = src[r0*64 + n];
    __syncthreads();

    const float* W1 = fw1 + iblk*8192;
    float b1v = fb1[iblk*128 + tid];
    float acc[8];
#pragma unroll
    for (int r = 0; r < 8; ++r) acc[r] = b1v;
#pragma unroll 8
    for (int k = 0; k < 64; ++k) {
        float w = W1[k*128 + tid];
#pragma unroll
        for (int r = 0; r < 8; ++r) acc[r] = fmaf(sx[r][k], w, acc[r]);
    }
#pragma unroll
    for (int r = 0; r < 8; ++r) sh[r][tid] = fmaxf(acc[r], 0.f);
    __syncthreads();

    const float* W2 = fw2 + iblk*8192;
    int c = tid & 63, g = tid >> 6;
    float b2v = fb2[iblk*64 + c];
    float a2[4];
#pragma unroll
    for (int r = 0; r < 4; ++r) a2[r] = b2v;
#pragma unroll 8
    for (int k = 0; k < 128; ++k) {
        float w = W2[k*64 + c];
#pragma unroll
        for (int r = 0; r < 4; ++r) a2[r] = fmaf(sh[g*4 + r][k], w, a2[r]);
    }
#pragma unroll
    for (int r = 0; r < 4; ++r) a2[r] += sx[g*4 + r][c];

    float s1[4], s2[4];
#pragma unroll
    for (int r = 0; r < 4; ++r) { s1[r] = a2[r]; s2[r] = a2[r]*a2[r]; }
#pragma unroll
    for (int off = 16; off; off >>= 1) {
#pragma unroll
        for (int r = 0; r < 4; ++r) {
            s1[r] += __shfl_xor_sync(0xffffffffu, s1[r], off);
            s2[r] += __shfl_xor_sync(0xffffffffu, s2[r], off);
        }
    }
    int lane = tid & 31, half = (tid >> 5) & 1;
    if (lane == 0) {
#pragma unroll
        for (int r = 0; r < 4; ++r) {
            sred[g*4 + r][half][0] = s1[r];
            sred[g*4 + r][half][1] = s2[r];
        }
    }
    __syncthreads();
    float nsv = ns[iblk*64 + c], nbv = nb[iblk*64 + c];
#pragma unroll
    for (int r = 0; r < 4; ++r) {
        int rr = g*4 + r;
        float tot  = sred[rr][0][0] + sred[rr][1][0];
        float tot2 = sred[rr][0][1] + sred[rr][1][1];
        float mu = tot * (1.f/64.f);
        float var = tot2 * (1.f/64.f) - mu*mu;
        float rstd = rsqrtf(var + 1e-6f);
        float y = (a2[r] - mu) * rstd * nsv + nbv;
        sy[rr][c] = y;
        dst[(r0 + rr)*64 + c] = y;
    }
    __syncthreads();

    if (nblk < 0) return;

    const float* Wm[3]; const float* Bm[3]; float* Dm[3]; int nmat;
    if (side == 0) {
        nmat = 1;
        Wm[0] = wq + nblk*4096; Bm[0] = bq + nblk*64; Dm[0] = g_q1;
    } else {
        nmat = 3;
        Wm[0] = wq + nblk*4096; Bm[0] = bq + nblk*64; Dm[0] = g_q2;
        Wm[1] = wk + nblk*4096; Bm[1] = bk + nblk*64; Dm[1] = g_kk;
        Wm[2] = wv + nblk*4096; Bm[2] = bv + nblk*64; Dm[2] = g_vv;
    }
    for (int mm = 0; mm < nmat; ++mm) {
        const float* W = Wm[mm];
        float bv = Bm[mm][c];
        float pa[4];
#pragma unroll
        for (int r = 0; r < 4; ++r) pa[r] = bv;
#pragma unroll 8
        for (int k = 0; k < 64; ++k) {
            float w = W[k*64 + c];
#pragma unroll
            for (int r = 0; r < 4; ++r) pa[r] = fmaf(sy[g*4 + r][k], w, pa[r]);
        }
#pragma unroll
        for (int r = 0; r < 4; ++r) Dm[mm][(r0 + g*4 + r)*64 + c] = pa[r];
    }
}

// ---------------------------------------------------------------------------
// Head
// ---------------------------------------------------------------------------
__global__ __launch_bounds__(128) void head_kernel(
    const float* __restrict__ fns, const float* __restrict__ fnb,
    const float* __restrict__ hw1, const float* __restrict__ hb1,
    const float* __restrict__ hw2, const float* __restrict__ hb2,
    float* __restrict__ out)
{
    __shared__ float sx[64], sh[128], sp0[128], sp1[128], sred[2];
    int row = blockIdx.x, tid = threadIdx.x;
    if (tid < 64) sx[tid] = g_qvs[row*64 + tid];
    __syncthreads();
    if (tid < 32) {
        float v0 = sx[tid], v1 = sx[tid + 32];
        float s = v0 + v1;
#pragma unroll
        for (int off = 16; off; off >>= 1)
            s += __shfl_xor_sync(0xffffffffu, s, off);
        float mu = s * (1.f/64.f);
        float e0 = v0 - mu, e1 = v1 - mu;
        float qv = fmaf(e0, e0, e1*e1);
#pragma unroll
        for (int off = 16; off; off >>= 1)
            qv += __shfl_xor_sync(0xffffffffu, qv, off);
        if (tid == 0) { sred[0] = mu; sred[1] = rsqrtf(qv*(1.f/64.f) + 1e-6f); }
    }
    __syncthreads();
    if (tid < 64) sx[tid] = (sx[tid] - sred[0]) * sred[1] * fns[tid] + fnb[tid];
    __syncthreads();
    float acc = hb1[tid];
#pragma unroll 16
    for (int k = 0; k < 64; ++k) acc = fmaf(sx[k], hw1[k*128 + tid], acc);
    sh[tid] = fmaxf(acc, 0.f);
    __syncthreads();
    sp0[tid] = sh[tid] * hw2[tid*2 + 0];
    sp1[tid] = sh[tid] * hw2[tid*2 + 1];
    __syncthreads();
    for (int s = 64; s > 0; s >>= 1) {
        if (tid < s) { sp0[tid] += sp0[tid + s]; sp1[tid] += sp1[tid + s]; }
        __syncthreads();
    }
    if (tid == 0) {
        out[row]        = sp0[0] + hb2[0];
        out[2048 + row] = __expf(0.5f * (sp1[0] + hb2[1]));
    }
}

// ---------------------------------------------------------------------------
extern "C" void kernel_launch(void* const* d_in, const int* in_sizes, int n_in,
                              void* d_out, int out_size)
{
    const float* s_ctx   = (const float*)d_in[0];
    const float* f_ctx   = (const float*)d_in[1];
    const float* s_test  = (const float*)d_in[2];
    const float* table   = (const float*)d_in[3];
    const float* emb_w1  = (const float*)d_in[4];
    const float* emb_b1  = (const float*)d_in[5];
    const float* emb_w2  = (const float*)d_in[6];
    const float* emb_b2  = (const float*)d_in[7];
    const float* attn_wq = (const float*)d_in[8];
    const float* attn_bq = (const float*)d_in[9];
    const float* attn_wk = (const float*)d_in[10];
    const float* attn_bk = (const float*)d_in[11];
    const float* attn_wv = (const float*)d_in[12];
    const float* attn_bv = (const float*)d_in[13];
    const float* attn_wo = (const float*)d_in[14];
    const float* attn_bo = (const float*)d_in[15];
    const float* ffn_w1  = (const float*)d_in[16];
    const float* ffn_b1  = (const float*)d_in[17];
    const float* ffn_w2  = (const float*)d_in[18];
    const float* ffn_b2  = (const float*)d_in[19];
    const float* bias_w1 = (const float*)d_in[20];
    const float* bias_b1 = (const float*)d_in[21];
    const float* bias_w2 = (const float*)d_in[22];
    const float* bias_b2 = (const float*)d_in[23];
    const float* norm_s  = (const float*)d_in[24];
    const float* norm_b  = (const float*)d_in[25];
    const float* fnorm_s = (const float*)d_in[26];
    const float* fnorm_b = (const float*)d_in[27];
    const float* head_w1 = (const float*)d_in[28];
    const float* head_b1 = (const float*)d_in[29];
    const float* head_w2 = (const float*)d_in[30];
    const float* head_b2 = (const float*)d_in[31];

    static int attr_done = 0;
    if (!attr_done) {
        cudaFuncSetAttribute(attn_kernel,
            cudaFuncAttributeMaxDynamicSharedMemorySize, 65536);
        attr_done = 1;
    }

    bias_setup_kernel<<<6, 32>>>(bias_w1, bias_b1, bias_w2, bias_b2);
    embed_kernel<<<4096, 256>>>(s_ctx, f_ctx, s_test, table,
                                emb_w1, emb_b1, emb_w2, emb_b2);
    proj_kernel<<<dim3(64, 4), 256>>>(0, attn_wq, attn_bq,
                                      attn_wk, attn_bk, attn_wv, attn_bv);
    for (int i = 0; i < 6; ++i) {
        attn_kernel<<<dim3(256, BB, 2), 256, 65536>>>(i, s_test, s_ctx,
                                                      attn_wo, attn_bo,
                                                      norm_s, norm_b);
        ffnproj_kernel<<<512, 128>>>(i, (i < 5) ? i + 1 : -1,
                                     ffn_w1, ffn_b1, ffn_w2, ffn_b2,
                                     norm_s, norm_b,
                                     attn_wq, attn_bq, attn_wk, attn_bk,
                                     attn_wv, attn_bv);
    }
    head_kernel<<<2048, 128>>>(fnorm_s, fnorm_b, head_w1, head_b1,
                               head_w2, head_b2, (float*)d_out);
}

// round 10
// speedup vs baseline: 1.3010x; 1.0842x over previous
#include <cuda_runtime.h>

#define BB 2
#define LL 1024
#define DD 64
#define NROWS (BB*LL)
#define SCALE 0.35355339059327373f
#define LOG2E 1.4426950408889634f
#define SCALE2 (SCALE * LOG2E)

// persistent activations (no allocation allowed)
__device__ float g_qvs[NROWS*DD];
__device__ float g_kvs[NROWS*DD];
__device__ float g_attq[NROWS*DD];
__device__ float g_attk[NROWS*DD];
__device__ float g_q1[NROWS*DD];
__device__ float g_q2[NROWS*DD];
__device__ float g_kk[NROWS*DD];
__device__ float g_vv[NROWS*DD];

// piecewise-linear distance-bias tables (per block), pre-scaled by log2(e)
__device__ float g_pl_t[6][16];
__device__ float g_pl_AC[6][17][16];
__device__ int   g_pl_i0[6];

__device__ __forceinline__ float ex2f(float x) {
    float r; asm("ex2.approx.f32 %0, %1;" : "=f"(r) : "f"(x)); return r;
}
__device__ __forceinline__ unsigned smem_u32(const void* p) {
    return (unsigned)__cvta_generic_to_shared(p);
}
__device__ __forceinline__ void cpa16(unsigned dst, const void* src) {
    asm volatile("cp.async.cg.shared.global [%0], [%1], 16;" :: "r"(dst), "l"(src));
}
__device__ __forceinline__ void cpa8(unsigned dst, const void* src) {
    asm volatile("cp.async.ca.shared.global [%0], [%1], 8;" :: "r"(dst), "l"(src));
}

// ---------------------------------------------------------------------------
// Setup: fold dist-bias MLP into 17-interval piecewise-linear form (x log2e).
// ---------------------------------------------------------------------------
__global__ void bias_setup_kernel(
    const float* __restrict__ bw1, const float* __restrict__ bb1,
    const float* __restrict__ bw2, const float* __restrict__ bb2)
{
    int i = blockIdx.x;
    if (threadIdx.x != 0) return;
    float w1[16], b1[16], t[16];
    for (int j = 0; j < 16; ++j) {
        w1[j] = bw1[i*16 + j];
        b1[j] = bb1[i*16 + j];
        t[j]  = (w1[j] != 0.f) ? (-b1[j] / w1[j]) : -1e30f;
    }
    int ord[16];
    for (int j = 0; j < 16; ++j) ord[j] = j;
    for (int a = 1; a < 16; ++a) {
        int o = ord[a]; float tv = t[o]; int b = a - 1;
        while (b >= 0 && t[ord[b]] > tv) { ord[b+1] = ord[b]; --b; }
        ord[b+1] = o;
    }
    int i0 = 0;
    for (int j = 0; j < 16; ++j) {
        g_pl_t[i][j] = t[ord[j]];
        if (t[ord[j]] <= 0.f) ++i0;
    }
    g_pl_i0[i] = i0;
    for (int m = 0; m <= 16; ++m) {
        float A[8], C[8];
        for (int h = 0; h < 8; ++h) { A[h] = 0.f; C[h] = 0.f; }
        for (int a = 0; a < 16; ++a) {
            int j = ord[a];
            bool act;
            if (w1[j] > 0.f)      act = (a < m);
            else if (w1[j] < 0.f) act = (a >= m);
            else                  act = (b1[j] > 0.f);
            if (act) {
                for (int h = 0; h < 8; ++h) {
                    A[h] += w1[j] * bw2[i*128 + j*8 + h];
                    C[h] += b1[j] * bw2[i*128 + j*8 + h];
                }
            }
        }
        for (int h = 0; h < 8; ++h) {
            g_pl_AC[i][m][h]     = A[h] * LOG2E;
            g_pl_AC[i][m][8 + h] = (C[h] + bb2[i*8 + h]) * LOG2E;
        }
    }
}

// ---------------------------------------------------------------------------
// Embed
// ---------------------------------------------------------------------------
__global__ __launch_bounds__(256) void embed_kernel(
    const float* __restrict__ s_ctx, const float* __restrict__ f_ctx,
    const float* __restrict__ s_test, const float* __restrict__ table,
    const float* __restrict__ w1, const float* __restrict__ b1,
    const float* __restrict__ w2, const float* __restrict__ b2)
{
    __shared__ float xs[8];
    __shared__ float h[256];
    __shared__ float part[256];
    int row = blockIdx.x, tid = threadIdx.x;
    int sideq = row >> 11;
    int r = row & 2047;
    int b = r >> 10, pos = r & 1023;
    if (tid < 7) {
        float v;
        if (sideq == 0) {
            v = (tid < 4) ? table[4 + tid]
              : (tid < 6) ? s_ctx[(b*LL + pos)*2 + tid - 4]
                          : f_ctx[b*LL + pos];
        } else {
            v = (tid < 4) ? table[tid]
              : (tid < 6) ? s_test[(b*LL + pos)*2 + tid - 4]
                          : 0.f;
        }
        xs[tid] = v;
    }
    __syncthreads();
    float acc = b1[tid];
#pragma unroll
    for (int i = 0; i < 7; ++i) acc = fmaf(xs[i], w1[i*256 + tid], acc);
    h[tid] = fmaxf(acc, 0.f);
    __syncthreads();
    int o = tid & 63, half = tid >> 6;
    float p = 0.f;
#pragma unroll 8
    for (int j = half*64; j < half*64 + 64; ++j) p = fmaf(h[j], w2[j*64 + o], p);
    part[tid] = p;
    __syncthreads();
    if (tid < 64) {
        float v = part[tid] + part[tid+64] + part[tid+128] + part[tid+192] + b2[tid];
        float* dst = sideq ? g_qvs : g_kvs;
        dst[(b*LL + pos)*64 + tid] = v;
    }
}

// ---------------------------------------------------------------------------
// Projections (block 0 only)
// ---------------------------------------------------------------------------
__global__ __launch_bounds__(256) void proj_kernel(
    int iblk,
    const float* __restrict__ wq, const float* __restrict__ bq,
    const float* __restrict__ wk, const float* __restrict__ bk,
    const float* __restrict__ wv, const float* __restrict__ bv)
{
    __shared__ float sW[64*64];
    __shared__ float sX[32*64];
    int tid = threadIdx.x;
    int mat = blockIdx.y;
    const float *X, *W, *bias; float* dst;
    if (mat == 0)      { X = g_qvs; W = wq + iblk*4096; bias = bq + iblk*64; dst = g_q1; }
    else if (mat == 1) { X = g_kvs; W = wq + iblk*4096; bias = bq + iblk*64; dst = g_q2; }
    else if (mat == 2) { X = g_kvs; W = wk + iblk*4096; bias = bk + iblk*64; dst = g_kk; }
    else               { X = g_kvs; W = wv + iblk*4096; bias = bv + iblk*64; dst = g_vv; }
    int row0 = blockIdx.x * 32;
    for (int n = tid; n < 4096; n += 256) sW[n] = W[n];
    for (int n = tid; n < 2048; n += 256) sX[n] = X[row0*64 + n];
    __syncthreads();
    int r = tid >> 3, c0 = (tid & 7) * 8;
    float acc[8];
#pragma unroll
    for (int i = 0; i < 8; ++i) acc[i] = bias[c0 + i];
#pragma unroll 16
    for (int k = 0; k < 64; ++k) {
        float a = sX[r*64 + k];
#pragma unroll
        for (int i = 0; i < 8; ++i) acc[i] = fmaf(a, sW[k*64 + c0 + i], acc[i]);
    }
#pragma unroll
    for (int i = 0; i < 8; ++i) dst[(row0 + r)*64 + c0 + i] = acc[i];
}

// ---------------------------------------------------------------------------
// Fused biased attention + out-proj + residual + LN.
// grid (128, B, 2). CTA = 8 warps = 8 queries. Warp = 4 queries x 2 heads
// (qq = wid>>2 selects query quad, hq = wid&3 selects head pair): every K/V
// LDS.128 feeds 8 FMAs. Q via broadcast LDS (1 wf each). cp.async double
// buffer; A/C hoisted to registers when i0==16 (bias_b1 == 0 case).
// ---------------------------------------------------------------------------
__global__ __launch_bounds__(256, 2) void attn_kernel(
    int iblk,
    const float* __restrict__ s_test, const float* __restrict__ s_ctx,
    const float* __restrict__ wo, const float* __restrict__ bo,
    const float* __restrict__ ns, const float* __restrict__ nb)
{
    // dynamic: K0[1024] V0[1024] K1[1024] V1[1024] float4 (64KB)
    extern __shared__ float4 dyn[];

    __shared__ float  sQ[512];      // 8 queries x 64, pre-scaled
    __shared__ float2 sSkA[128];    // double-buffered key coords
    __shared__ float2 sAC2[136];
    __shared__ float  sO[512];
    __shared__ float  sRed[8][2][2];

    const int tid = threadIdx.x, wid = tid >> 5, lane = tid & 31;
    const int side = blockIdx.z, b = blockIdx.y;
    const int qq = wid >> 2;            // query quad (0/1)
    const int hq = wid & 3;             // head pair
    const int q0 = blockIdx.x*8 + qq*4; // first of this warp's 4 queries

    const float* Qp  = side ? g_q2 : g_q1;
    const float* sqc = side ? s_ctx : s_test;

    for (int n = tid; n < 272; n += 256)
        ((float*)sAC2)[n] = ((const float*)g_pl_AC)[iblk*272 + n];
    sQ[tid]       = Qp[(b*LL + blockIdx.x*8)*64 + tid] * SCALE2;
    sQ[256 + tid] = Qp[(b*LL + blockIdx.x*8)*64 + 256 + tid] * SCALE2;

    const int i0 = g_pl_i0[iblk];
    const float* trg = g_pl_t[iblk];
    float qx[4], qy[4];
#pragma unroll
    for (int qi = 0; qi < 4; ++qi) {
        qx[qi] = sqc[(b*LL + q0 + qi)*2];
        qy[qi] = sqc[(b*LL + q0 + qi)*2 + 1];
    }

    float l[8];
#pragma unroll
    for (int i = 0; i < 8; ++i) l[i] = 0.f;
    float o[64];
#pragma unroll
    for (int d = 0; d < 64; ++d) o[d] = 0.f;

    const int ksw = lane & 15, kb0 = lane << 4;
    int ikk[4];
#pragma unroll
    for (int cc = 0; cc < 4; ++cc) ikk[cc] = kb0 + ((4*hq + cc) ^ ksw);

    const float4* Kg = (const float4*)(g_kk + b*LL*64);
    const float4* Vg = (const float4*)(g_vv + b*LL*64);
    const float2* Skg = (const float2*)s_ctx + b*LL;

    // staging: 4 float4 per thread per buffer; u32 smem addrs precomputed
    int sgN[4]; unsigned sgU[4];
#pragma unroll
    for (int n4 = 0; n4 < 4; ++n4) {
        int n = n4*256 + tid;
        int kr = n >> 4, c = n & 15;
        sgN[n4] = n;
        sgU[n4] = (unsigned)(((kr << 4) + (c ^ (kr & 15))) * 16);
    }
    const unsigned uK0 = smem_u32(dyn);
    const unsigned uV0 = uK0 + 16384;
    const unsigned uK1 = uK0 + 32768;
    const unsigned uV1 = uK0 + 49152;
    const unsigned uSk = smem_u32(sSkA);

    __syncthreads();   // sQ / sAC2 visible
    const float2 A16 = sAC2[16*8 + hq];
    const float2 C16 = sAC2[16*8 + 4 + hq];

    // prologue: stage tile 0 into buffer 0
#pragma unroll
    for (int n4 = 0; n4 < 4; ++n4) {
        cpa16(uK0 + sgU[n4], Kg + sgN[n4]);
        cpa16(uV0 + sgU[n4], Vg + sgN[n4]);
    }
    if (tid < 64) cpa8(uSk + tid*8, Skg + tid);
    asm volatile("cp.async.commit_group;");

    for (int t = 0; t < 16; ++t) {
        const int bf = t & 1;
        if (t + 1 < 16) {
            const unsigned uK = bf ? uK0 : uK1;
            const unsigned uV = bf ? uV0 : uV1;
#pragma unroll
            for (int n4 = 0; n4 < 4; ++n4) {
                cpa16(uK + sgU[n4], Kg + (t+1)*1024 + sgN[n4]);
                cpa16(uV + sgU[n4], Vg + (t+1)*1024 + sgN[n4]);
            }
            if (tid < 64) cpa8(uSk + (bf ? 0u : 512u) + tid*8, Skg + (t+1)*64 + tid);
            asm volatile("cp.async.commit_group;");
            asm volatile("cp.async.wait_group 1;");
        } else {
            asm volatile("cp.async.wait_group 0;");
        }
        __syncthreads();

        const float4* sK = bf ? (dyn + 2048) : dyn;
        const float4* sV = bf ? (dyn + 3072) : (dyn + 1024);
        const float2* sSk = sSkA + bf*64;

        float2 ck0 = sSk[lane], ck1 = sSk[lane + 32];
        float d0[4], d1[4];
#pragma unroll
        for (int qi = 0; qi < 4; ++qi) {
            float dx = qx[qi] - ck0.x, dy = qy[qi] - ck0.y;
            d0[qi] = fmaf(dx, dx, dy*dy);
            dx = qx[qi] - ck1.x; dy = qy[qi] - ck1.y;
            d1[qi] = fmaf(dx, dx, dy*dy);
        }

        // s[qi*4 + kk*2 + h]
        float s[16];
        if (i0 == 16) {     // all breakpoints <= 0 (bias_b1 == 0): m == 16
#pragma unroll
            for (int qi = 0; qi < 4; ++qi) {
                s[qi*4+0] = fmaf(A16.x, d0[qi], C16.x);
                s[qi*4+1] = fmaf(A16.y, d0[qi], C16.y);
                s[qi*4+2] = fmaf(A16.x, d1[qi], C16.x);
                s[qi*4+3] = fmaf(A16.y, d1[qi], C16.y);
            }
        } else {            // general fallback
#pragma unroll
            for (int qi = 0; qi < 4; ++qi) {
                int m0 = i0, m1 = i0;
                for (int i = i0; i < 16; ++i) {
                    float tv = trg[i];
                    m0 += d0[qi] > tv; m1 += d1[qi] > tv;
                }
                float2 Aa = sAC2[m0*8 + hq], Ca = sAC2[m0*8 + 4 + hq];
                float2 Ab = sAC2[m1*8 + hq], Cb = sAC2[m1*8 + 4 + hq];
                s[qi*4+0] = fmaf(Aa.x, d0[qi], Ca.x);
                s[qi*4+1] = fmaf(Aa.y, d0[qi], Ca.y);
                s[qi*4+2] = fmaf(Ab.x, d1[qi], Cb.x);
                s[qi*4+3] = fmaf(Ab.y, d1[qi], Cb.y);
            }
        }

        // QK dots: each K load feeds 4 queries (Q broadcast, pre-scaled)
        const float4* sQ4 = ((const float4*)sQ) + qq*64 + 4*hq;
#pragma unroll
        for (int cc = 0; cc < 4; ++cc) {
            const int h = cc >> 1;
            float4 k0 = sK[ikk[cc]];
            float4 k1 = sK[ikk[cc] + 512];
#pragma unroll
            for (int qi = 0; qi < 4; ++qi) {
                float4 qv = sQ4[qi*16 + cc];
                s[qi*4+h]   = fmaf(qv.x, k0.x, s[qi*4+h]);
                s[qi*4+h]   = fmaf(qv.y, k0.y, s[qi*4+h]);
                s[qi*4+h]   = fmaf(qv.z, k0.z, s[qi*4+h]);
                s[qi*4+h]   = fmaf(qv.w, k0.w, s[qi*4+h]);
                s[qi*4+2+h] = fmaf(qv.x, k1.x, s[qi*4+2+h]);
                s[qi*4+2+h] = fmaf(qv.y, k1.y, s[qi*4+2+h]);
                s[qi*4+2+h] = fmaf(qv.z, k1.z, s[qi*4+2+h]);
                s[qi*4+2+h] = fmaf(qv.w, k1.w, s[qi*4+2+h]);
            }
        }

        float pr[16];
#pragma unroll
        for (int i = 0; i < 16; ++i) pr[i] = ex2f(s[i]);
#pragma unroll
        for (int qi = 0; qi < 4; ++qi) {
            l[qi*2+0] += pr[qi*4+0] + pr[qi*4+2];
            l[qi*2+1] += pr[qi*4+1] + pr[qi*4+3];
        }

        // V accumulation: each V load feeds 4 queries
#pragma unroll
        for (int cc = 0; cc < 4; ++cc) {
            const int h = cc >> 1, dc = (cc & 1) * 4;
            float4 v0 = sV[ikk[cc]];
            float4 v1 = sV[ikk[cc] + 512];
#pragma unroll
            for (int qi = 0; qi < 4; ++qi) {
                const int ob = qi*16 + h*8 + dc;
                float pa = pr[qi*4+h], pb = pr[qi*4+2+h];
                o[ob+0] = fmaf(pa, v0.x, o[ob+0]);
                o[ob+0] = fmaf(pb, v1.x, o[ob+0]);
                o[ob+1] = fmaf(pa, v0.y, o[ob+1]);
                o[ob+1] = fmaf(pb, v1.y, o[ob+1]);
                o[ob+2] = fmaf(pa, v0.z, o[ob+2]);
                o[ob+2] = fmaf(pb, v1.z, o[ob+2]);
                o[ob+3] = fmaf(pa, v0.w, o[ob+3]);
                o[ob+3] = fmaf(pb, v1.w, o[ob+3]);
            }
        }
        __syncthreads();   // all done reading buf bf before restaging
    }

    // merge lanes (butterfly)
#pragma unroll
    for (int i = 0; i < 8; ++i) {
        float lh = l[i];
#pragma unroll
        for (int off = 16; off; off >>= 1)
            lh += __shfl_xor_sync(0xffffffffu, lh, off);
        l[i] = lh;
    }
#pragma unroll
    for (int d = 0; d < 64; ++d) {
        float v = o[d];
#pragma unroll
        for (int off = 16; off; off >>= 1)
            v += __shfl_xor_sync(0xffffffffu, v, off);
        o[d] = v;
    }
    float inv[8];
#pragma unroll
    for (int i = 0; i < 8; ++i) inv[i] = 1.f / l[i];
#pragma unroll
    for (int d = 0; d < 64; ++d) o[d] *= inv[(d >> 4)*2 + ((d >> 3) & 1)];

    // lane i extracts o[i] and o[32+i]
    float mv0 = 0.f, mv1 = 0.f;
#pragma unroll
    for (int i = 0; i < 32; ++i)
        if (lane == i) { mv0 = o[i]; mv1 = o[32 + i]; }

    sO[(qq*4 + (lane >> 4))*64     + hq*16 + (lane & 15)] = mv0;
    sO[(qq*4 + 2 + (lane >> 4))*64 + hq*16 + (lane & 15)] = mv1;

    // stage Wo into dyn (all warps past final tile barrier)
    float* sWo = (float*)dyn;
    const float* Wog = wo + iblk*4096;
    for (int n = tid; n < 4096; n += 256) sWo[n] = Wog[n];
    __syncthreads();

    // out-proj + residual + LN for queries qA = tid>>6 and qB = qA+4
    const int c = tid & 63, qA = tid >> 6, qB = qA + 4;
    const int rowA = b*LL + blockIdx.x*8 + qA;
    const int rowB = rowA + 4;
    float accA = bo[iblk*64 + c], accB = accA;
#pragma unroll 16
    for (int i = 0; i < 64; ++i) {
        float w = sWo[i*64 + c];
        accA = fmaf(sO[qA*64 + i], w, accA);
        accB = fmaf(sO[qB*64 + i], w, accB);
    }
    const float* src = side ? g_kvs : g_qvs;
    accA += src[rowA*64 + c];
    accB += src[rowB*64 + c];

    float s1A = accA, s2A = accA*accA, s1B = accB, s2B = accB*accB;
#pragma unroll
    for (int off = 16; off; off >>= 1) {
        s1A += __shfl_xor_sync(0xffffffffu, s1A, off);
        s2A += __shfl_xor_sync(0xffffffffu, s2A, off);
        s1B += __shfl_xor_sync(0xffffffffu, s1B, off);
        s2B += __shfl_xor_sync(0xffffffffu, s2B, off);
    }
    const int half = (tid >> 5) & 1;
    if (lane == 0) {
        sRed[qA][half][0] = s1A; sRed[qA][half][1] = s2A;
        sRed[qB][half][0] = s1B; sRed[qB][half][1] = s2B;
    }
    __syncthreads();
    float* outp = side ? g_attk : g_attq;
    const float nsv = ns[iblk*64 + c], nbv = nb[iblk*64 + c];
    {
        float tot  = sRed[qA][0][0] + sRed[qA][1][0];
        float tot2 = sRed[qA][0][1] + sRed[qA][1][1];
        float mu = tot * (1.f/64.f);
        float var = tot2 * (1.f/64.f) - mu*mu;
        float rstd = rsqrtf(var + 1e-6f);
        outp[rowA*64 + c] = (accA - mu) * rstd * nsv + nbv;
    }
    {
        float tot  = sRed[qB][0][0] + sRed[qB][1][0];
        float tot2 = sRed[qB][0][1] + sRed[qB][1][1];
        float mu = tot * (1.f/64.f);
        float var = tot2 * (1.f/64.f) - mu*mu;
        float rstd = rsqrtf(var + 1e-6f);
        outp[rowB*64 + c] = (accB - mu) * rstd * nsv + nbv;
    }
}

// ---------------------------------------------------------------------------
// FFN + residual + LN + next-block projections.
// ---------------------------------------------------------------------------
__global__ __launch_bounds__(128) void ffnproj_kernel(
    int iblk, int nblk,
    const float* __restrict__ fw1, const float* __restrict__ fb1,
    const float* __restrict__ fw2, const float* __restrict__ fb2,
    const float* __restrict__ ns, const float* __restrict__ nb,
    const float* __restrict__ wq, const float* __restrict__ bq,
    const float* __restrict__ wk, const float* __restrict__ bk,
    const float* __restrict__ wv, const float* __restrict__ bv)
{
    __shared__ float sx[8][64];
    __shared__ float sh[8][128];
    __shared__ float sy[8][64];
    __shared__ float sred[8][2][2];

    int tid = threadIdx.x;
    int row0 = blockIdx.x * 8;
    int side = row0 >> 11;
    int r0 = row0 & 2047;
    const float* src = side ? g_attk : g_attq;
    float* dst = side ? g_kvs : g_qvs;

    for (int n = tid; n < 512; n += 128) sx[n >> 6][n & 63] = src[r0*64 + n];
    __syncthreads();

    const float* W1 = fw1 + iblk*8192;
    float b1v = fb1[iblk*128 + tid];
    float acc[8];
#pragma unroll
    for (int r = 0; r < 8; ++r) acc[r] = b1v;
#pragma unroll 8
    for (int k = 0; k < 64; ++k) {
        float w = W1[k*128 + tid];
#pragma unroll
        for (int r = 0; r < 8; ++r) acc[r] = fmaf(sx[r][k], w, acc[r]);
    }
#pragma unroll
    for (int r = 0; r < 8; ++r) sh[r][tid] = fmaxf(acc[r], 0.f);
    __syncthreads();

    const float* W2 = fw2 + iblk*8192;
    int c = tid & 63, g = tid >> 6;
    float b2v = fb2[iblk*64 + c];
    float a2[4];
#pragma unroll
    for (int r = 0; r < 4; ++r) a2[r] = b2v;
#pragma unroll 8
    for (int k = 0; k < 128; ++k) {
        float w = W2[k*64 + c];
#pragma unroll
        for (int r = 0; r < 4; ++r) a2[r] = fmaf(sh[g*4 + r][k], w, a2[r]);
    }
#pragma unroll
    for (int r = 0; r < 4; ++r) a2[r] += sx[g*4 + r][c];

    float s1[4], s2[4];
#pragma unroll
    for (int r = 0; r < 4; ++r) { s1[r] = a2[r]; s2[r] = a2[r]*a2[r]; }
#pragma unroll
    for (int off = 16; off; off >>= 1) {
#pragma unroll
        for (int r = 0; r < 4; ++r) {
            s1[r] += __shfl_xor_sync(0xffffffffu, s1[r], off);
            s2[r] += __shfl_xor_sync(0xffffffffu, s2[r], off);
        }
    }
    int lane = tid & 31, half = (tid >> 5) & 1;
    if (lane == 0) {
#pragma unroll
        for (int r = 0; r < 4; ++r) {
            sred[g*4 + r][half][0] = s1[r];
            sred[g*4 + r][half][1] = s2[r];
        }
    }
    __syncthreads();
    float nsv = ns[iblk*64 + c], nbv = nb[iblk*64 + c];
#pragma unroll
    for (int r = 0; r < 4; ++r) {
        int rr = g*4 + r;
        float tot  = sred[rr][0][0] + sred[rr][1][0];
        float tot2 = sred[rr][0][1] + sred[rr][1][1];
        float mu = tot * (1.f/64.f);
        float var = tot2 * (1.f/64.f) - mu*mu;
        float rstd = rsqrtf(var + 1e-6f);
        float y = (a2[r] - mu) * rstd * nsv + nbv;
        sy[rr][c] = y;
        dst[(r0 + rr)*64 + c] = y;
    }
    __syncthreads();

    if (nblk < 0) return;

    const float* Wm[3]; const float* Bm[3]; float* Dm[3]; int nmat;
    if (side == 0) {
        nmat = 1;
        Wm[0] = wq + nblk*4096; Bm[0] = bq + nblk*64; Dm[0] = g_q1;
    } else {
        nmat = 3;
        Wm[0] = wq + nblk*4096; Bm[0] = bq + nblk*64; Dm[0] = g_q2;
        Wm[1] = wk + nblk*4096; Bm[1] = bk + nblk*64; Dm[1] = g_kk;
        Wm[2] = wv + nblk*4096; Bm[2] = bv + nblk*64; Dm[2] = g_vv;
    }
    for (int mm = 0; mm < nmat; ++mm) {
        const float* W = Wm[mm];
        float bv = Bm[mm][c];
        float pa[4];
#pragma unroll
        for (int r = 0; r < 4; ++r) pa[r] = bv;
#pragma unroll 8
        for (int k = 0; k < 64; ++k) {
            float w = W[k*64 + c];
#pragma unroll
            for (int r = 0; r < 4; ++r) pa[r] = fmaf(sy[g*4 + r][k], w, pa[r]);
        }
#pragma unroll
        for (int r = 0; r < 4; ++r) Dm[mm][(r0 + g*4 + r)*64 + c] = pa[r];
    }
}

// ---------------------------------------------------------------------------
// Head
// ---------------------------------------------------------------------------
__global__ __launch_bounds__(128) void head_kernel(
    const float* __restrict__ fns, const float* __restrict__ fnb,
    const float* __restrict__ hw1, const float* __restrict__ hb1,
    const float* __restrict__ hw2, const float* __restrict__ hb2,
    float* __restrict__ out)
{
    __shared__ float sx[64], sh[128], sp0[128], sp1[128], sred[2];
    int row = blockIdx.x, tid = threadIdx.x;
    if (tid < 64) sx[tid] = g_qvs[row*64 + tid];
    __syncthreads();
    if (tid < 32) {
        float v0 = sx[tid], v1 = sx[tid + 32];
        float s = v0 + v1;
#pragma unroll
        for (int off = 16; off; off >>= 1)
            s += __shfl_xor_sync(0xffffffffu, s, off);
        float mu = s * (1.f/64.f);
        float e0 = v0 - mu, e1 = v1 - mu;
        float qv = fmaf(e0, e0, e1*e1);
#pragma unroll
        for (int off = 16; off; off >>= 1)
            qv += __shfl_xor_sync(0xffffffffu, qv, off);
        if (tid == 0) { sred[0] = mu; sred[1] = rsqrtf(qv*(1.f/64.f) + 1e-6f); }
    }
    __syncthreads();
    if (tid < 64) sx[tid] = (sx[tid] - sred[0]) * sred[1] * fns[tid] + fnb[tid];
    __syncthreads();
    float acc = hb1[tid];
#pragma unroll 16
    for (int k = 0; k < 64; ++k) acc = fmaf(sx[k], hw1[k*128 + tid], acc);
    sh[tid] = fmaxf(acc, 0.f);
    __syncthreads();
    sp0[tid] = sh[tid] * hw2[tid*2 + 0];
    sp1[tid] = sh[tid] * hw2[tid*2 + 1];
    __syncthreads();
    for (int s = 64; s > 0; s >>= 1) {
        if (tid < s) { sp0[tid] += sp0[tid + s]; sp1[tid] += sp1[tid + s]; }
        __syncthreads();
    }
    if (tid == 0) {
        out[row]        = sp0[0] + hb2[0];
        out[2048 + row] = __expf(0.5f * (sp1[0] + hb2[1]));
    }
}

// ---------------------------------------------------------------------------
extern "C" void kernel_launch(void* const* d_in, const int* in_sizes, int n_in,
                              void* d_out, int out_size)
{
    const float* s_ctx   = (const float*)d_in[0];
    const float* f_ctx   = (const float*)d_in[1];
    const float* s_test  = (const float*)d_in[2];
    const float* table   = (const float*)d_in[3];
    const float* emb_w1  = (const float*)d_in[4];
    const float* emb_b1  = (const float*)d_in[5];
    const float* emb_w2  = (const float*)d_in[6];
    const float* emb_b2  = (const float*)d_in[7];
    const float* attn_wq = (const float*)d_in[8];
    const float* attn_bq = (const float*)d_in[9];
    const float* attn_wk = (const float*)d_in[10];
    const float* attn_bk = (const float*)d_in[11];
    const float* attn_wv = (const float*)d_in[12];
    const float* attn_bv = (const float*)d_in[13];
    const float* attn_wo = (const float*)d_in[14];
    const float* attn_bo = (const float*)d_in[15];
    const float* ffn_w1  = (const float*)d_in[16];
    const float* ffn_b1  = (const float*)d_in[17];
    const float* ffn_w2  = (const float*)d_in[18];
    const float* ffn_b2  = (const float*)d_in[19];
    const float* bias_w1 = (const float*)d_in[20];
    const float* bias_b1 = (const float*)d_in[21];
    const float* bias_w2 = (const float*)d_in[22];
    const float* bias_b2 = (const float*)d_in[23];
    const float* norm_s  = (const float*)d_in[24];
    const float* norm_b  = (const float*)d_in[25];
    const float* fnorm_s = (const float*)d_in[26];
    const float* fnorm_b = (const float*)d_in[27];
    const float* head_w1 = (const float*)d_in[28];
    const float* head_b1 = (const float*)d_in[29];
    const float* head_w2 = (const float*)d_in[30];
    const float* head_b2 = (const float*)d_in[31];

    static int attr_done = 0;
    if (!attr_done) {
        cudaFuncSetAttribute(attn_kernel,
            cudaFuncAttributeMaxDynamicSharedMemorySize, 65536);
        attr_done = 1;
    }

    bias_setup_kernel<<<6, 32>>>(bias_w1, bias_b1, bias_w2, bias_b2);
    embed_kernel<<<4096, 256>>>(s_ctx, f_ctx, s_test, table,
                                emb_w1, emb_b1, emb_w2, emb_b2);
    proj_kernel<<<dim3(64, 4), 256>>>(0, attn_wq, attn_bq,
                                      attn_wk, attn_bk, attn_wv, attn_bv);
    for (int i = 0; i < 6; ++i) {
        attn_kernel<<<dim3(128, BB, 2), 256, 65536>>>(i, s_test, s_ctx,
                                                      attn_wo, attn_bo,
                                                      norm_s, norm_b);
        ffnproj_kernel<<<512, 128>>>(i, (i < 5) ? i + 1 : -1,
                                     ffn_w1, ffn_b1, ffn_w2, ffn_b2,
                                     norm_s, norm_b,
                                     attn_wq, attn_bq, attn_wk, attn_bk,
                                     attn_wv, attn_bv);
    }
    head_kernel<<<2048, 128>>>(fnorm_s, fnorm_b, head_w1, head_b1,
                               head_w2, head_b2, (float*)d_out);
}

// round 11
// speedup vs baseline: 1.3323x; 1.0241x over previous
#include <cuda_runtime.h>

#define BB 2
#define LL 1024
#define DD 64
#define NROWS (BB*LL)
#define SCALE 0.35355339059327373f
#define LOG2E 1.4426950408889634f
#define SCALE2 (SCALE * LOG2E)

// persistent activations (no allocation allowed)
__device__ float g_qvs[NROWS*DD];
__device__ float g_kvs[NROWS*DD];
__device__ float g_attq[NROWS*DD];
__device__ float g_attk[NROWS*DD];
__device__ float g_q1[NROWS*DD];
__device__ float g_q2[NROWS*DD];
__device__ float g_kk[NROWS*DD];
__device__ float g_vv[NROWS*DD];

// piecewise-linear distance-bias tables (per block), pre-scaled by log2(e)
__device__ float g_pl_t[6][16];
__device__ float g_pl_AC[6][17][16];
__device__ int   g_pl_i0[6];

__device__ __forceinline__ float ex2f(float x) {
    float r; asm("ex2.approx.f32 %0, %1;" : "=f"(r) : "f"(x)); return r;
}
__device__ __forceinline__ unsigned smem_u32(const void* p) {
    return (unsigned)__cvta_generic_to_shared(p);
}
__device__ __forceinline__ void cpa16(unsigned dst, const void* src) {
    asm volatile("cp.async.cg.shared.global [%0], [%1], 16;" :: "r"(dst), "l"(src));
}
__device__ __forceinline__ void cpa8(unsigned dst, const void* src) {
    asm volatile("cp.async.ca.shared.global [%0], [%1], 8;" :: "r"(dst), "l"(src));
}

// ---------------------------------------------------------------------------
// Setup: fold dist-bias MLP into 17-interval piecewise-linear form (x log2e).
// ---------------------------------------------------------------------------
__global__ void bias_setup_kernel(
    const float* __restrict__ bw1, const float* __restrict__ bb1,
    const float* __restrict__ bw2, const float* __restrict__ bb2)
{
    int i = blockIdx.x;
    if (threadIdx.x != 0) return;
    float w1[16], b1[16], t[16];
    for (int j = 0; j < 16; ++j) {
        w1[j] = bw1[i*16 + j];
        b1[j] = bb1[i*16 + j];
        t[j]  = (w1[j] != 0.f) ? (-b1[j] / w1[j]) : -1e30f;
    }
    int ord[16];
    for (int j = 0; j < 16; ++j) ord[j] = j;
    for (int a = 1; a < 16; ++a) {
        int o = ord[a]; float tv = t[o]; int b = a - 1;
        while (b >= 0 && t[ord[b]] > tv) { ord[b+1] = ord[b]; --b; }
        ord[b+1] = o;
    }
    int i0 = 0;
    for (int j = 0; j < 16; ++j) {
        g_pl_t[i][j] = t[ord[j]];
        if (t[ord[j]] <= 0.f) ++i0;
    }
    g_pl_i0[i] = i0;
    for (int m = 0; m <= 16; ++m) {
        float A[8], C[8];
        for (int h = 0; h < 8; ++h) { A[h] = 0.f; C[h] = 0.f; }
        for (int a = 0; a < 16; ++a) {
            int j = ord[a];
            bool act;
            if (w1[j] > 0.f)      act = (a < m);
            else if (w1[j] < 0.f) act = (a >= m);
            else                  act = (b1[j] > 0.f);
            if (act) {
                for (int h = 0; h < 8; ++h) {
                    A[h] += w1[j] * bw2[i*128 + j*8 + h];
                    C[h] += b1[j] * bw2[i*128 + j*8 + h];
                }
            }
        }
        for (int h = 0; h < 8; ++h) {
            g_pl_AC[i][m][h]     = A[h] * LOG2E;
            g_pl_AC[i][m][8 + h] = (C[h] + bb2[i*8 + h]) * LOG2E;
        }
    }
}

// ---------------------------------------------------------------------------
// Embed: 4 rows/CTA, each w1/w2 load reused by 4 rows. grid 1024, 256 thr.
// ---------------------------------------------------------------------------
__global__ __launch_bounds__(256) void embed_kernel(
    const float* __restrict__ s_ctx, const float* __restrict__ f_ctx,
    const float* __restrict__ s_test, const float* __restrict__ table,
    const float* __restrict__ w1, const float* __restrict__ b1,
    const float* __restrict__ w2, const float* __restrict__ b2)
{
    __shared__ float xs[4][8];
    __shared__ float h4[4][256];
    __shared__ float part[4][256];
    int tid = threadIdx.x;
    int row0 = blockIdx.x * 4;
    int sideq = row0 >> 11;
    if (tid < 32) {
        int r = tid >> 3, i = tid & 7;
        if (i < 7) {
            int row = (row0 + r) & 2047;
            int b = row >> 10, pos = row & 1023;
            float v;
            if (sideq == 0) {
                v = (i < 4) ? table[4 + i]
                  : (i < 6) ? s_ctx[(b*LL + pos)*2 + i - 4]
                            : f_ctx[b*LL + pos];
            } else {
                v = (i < 4) ? table[i]
                  : (i < 6) ? s_test[(b*LL + pos)*2 + i - 4]
                            : 0.f;
            }
            xs[r][i] = v;
        }
    }
    __syncthreads();
    float b1v = b1[tid];
    float a0 = b1v, a1 = b1v, a2 = b1v, a3 = b1v;
#pragma unroll
    for (int i = 0; i < 7; ++i) {
        float w = w1[i*256 + tid];
        a0 = fmaf(xs[0][i], w, a0);
        a1 = fmaf(xs[1][i], w, a1);
        a2 = fmaf(xs[2][i], w, a2);
        a3 = fmaf(xs[3][i], w, a3);
    }
    h4[0][tid] = fmaxf(a0, 0.f); h4[1][tid] = fmaxf(a1, 0.f);
    h4[2][tid] = fmaxf(a2, 0.f); h4[3][tid] = fmaxf(a3, 0.f);
    __syncthreads();
    int oc = tid & 63, g = tid >> 6;
    float p0 = 0.f, p1 = 0.f, p2 = 0.f, p3 = 0.f;
#pragma unroll 8
    for (int j = g*64; j < g*64 + 64; ++j) {
        float w = w2[j*64 + oc];
        p0 = fmaf(h4[0][j], w, p0);
        p1 = fmaf(h4[1][j], w, p1);
        p2 = fmaf(h4[2][j], w, p2);
        p3 = fmaf(h4[3][j], w, p3);
    }
    part[0][tid] = p0; part[1][tid] = p1; part[2][tid] = p2; part[3][tid] = p3;
    __syncthreads();
    {
        int r = tid >> 6, col = tid & 63;
        float v = part[r][col] + part[r][64 + col] + part[r][128 + col]
                + part[r][192 + col] + b2[col];
        int rr = (row0 + r) & 2047;
        float* dst = sideq ? g_qvs : g_kvs;
        dst[rr*64 + col] = v;
    }
}

// ---------------------------------------------------------------------------
// Projections (block 0 only)
// ---------------------------------------------------------------------------
__global__ __launch_bounds__(256) void proj_kernel(
    int iblk,
    const float* __restrict__ wq, const float* __restrict__ bq,
    const float* __restrict__ wk, const float* __restrict__ bk,
    const float* __restrict__ wv, const float* __restrict__ bv)
{
    __shared__ float sW[64*64];
    __shared__ float sX[32*64];
    int tid = threadIdx.x;
    int mat = blockIdx.y;
    const float *X, *W, *bias; float* dst;
    if (mat == 0)      { X = g_qvs; W = wq + iblk*4096; bias = bq + iblk*64; dst = g_q1; }
    else if (mat == 1) { X = g_kvs; W = wq + iblk*4096; bias = bq + iblk*64; dst = g_q2; }
    else if (mat == 2) { X = g_kvs; W = wk + iblk*4096; bias = bk + iblk*64; dst = g_kk; }
    else               { X = g_kvs; W = wv + iblk*4096; bias = bv + iblk*64; dst = g_vv; }
    int row0 = blockIdx.x * 32;
    for (int n = tid; n < 4096; n += 256) sW[n] = W[n];
    for (int n = tid; n < 2048; n += 256) sX[n] = X[row0*64 + n];
    __syncthreads();
    int r = tid >> 3, c0 = (tid & 7) * 8;
    float acc[8];
#pragma unroll
    for (int i = 0; i < 8; ++i) acc[i] = bias[c0 + i];
#pragma unroll 16
    for (int k = 0; k < 64; ++k) {
        float a = sX[r*64 + k];
#pragma unroll
        for (int i = 0; i < 8; ++i) acc[i] = fmaf(a, sW[k*64 + c0 + i], acc[i]);
    }
#pragma unroll
    for (int i = 0; i < 8; ++i) dst[(row0 + r)*64 + c0 + i] = acc[i];
}

// ---------------------------------------------------------------------------
// Fused biased attention + out-proj + residual + LN.
// grid (128, B, 2). CTA = 8 warps = 8 queries. Warp w = head w, ALL 8 queries:
// each K/V smem column read by exactly one warp. Distances computed
// cooperatively (warp w computes query w's row into sD). cp.async double
// buffer with restage after the visibility barrier.
// ---------------------------------------------------------------------------
__global__ __launch_bounds__(256, 2) void attn_kernel(
    int iblk,
    const float* __restrict__ s_test, const float* __restrict__ s_ctx,
    const float* __restrict__ wo, const float* __restrict__ bo,
    const float* __restrict__ ns, const float* __restrict__ nb)
{
    // dynamic: K0[1024] V0[1024] K1[1024] V1[1024] float4 (64KB)
    extern __shared__ float4 dyn[];

    __shared__ float  sQ[512];      // 8 queries x 64, pre-scaled
    __shared__ float2 sSkA[128];    // double-buffered key coords
    __shared__ float2 sQc[8];       // query coords
    __shared__ float  sD[512];      // 8 queries x 64 distances (current tile)
    __shared__ float  sAC[272];     // PL tables
    __shared__ float  sO[512];
    __shared__ float  sRed[8][2][2];

    const int tid = threadIdx.x, wid = tid >> 5, lane = tid & 31;
    const int side = blockIdx.z, b = blockIdx.y;

    const float* Qp  = side ? g_q2 : g_q1;
    const float* sqc = side ? s_ctx : s_test;

    for (int n = tid; n < 272; n += 256)
        sAC[n] = ((const float*)g_pl_AC)[iblk*272 + n];
    sQ[tid]       = Qp[(b*LL + blockIdx.x*8)*64 + tid] * SCALE2;
    sQ[256 + tid] = Qp[(b*LL + blockIdx.x*8)*64 + 256 + tid] * SCALE2;
    if (tid < 8) sQc[tid] = ((const float2*)sqc)[b*LL + blockIdx.x*8 + tid];

    const int i0 = g_pl_i0[iblk];
    const float* trg = g_pl_t[iblk];

    float l[8];
#pragma unroll
    for (int i = 0; i < 8; ++i) l[i] = 0.f;
    float o[64];
#pragma unroll
    for (int d = 0; d < 64; ++d) o[d] = 0.f;

    const int ksw = lane & 15, kb0 = lane << 4;
    const int ikk0 = kb0 + ((2*wid)     ^ ksw);
    const int ikk1 = kb0 + ((2*wid + 1) ^ ksw);

    const float4* Kg = (const float4*)(g_kk + b*LL*64);
    const float4* Vg = (const float4*)(g_vv + b*LL*64);
    const float2* Skg = (const float2*)s_ctx + b*LL;

    int sgN[4]; unsigned sgU[4];
#pragma unroll
    for (int n4 = 0; n4 < 4; ++n4) {
        int n = n4*256 + tid;
        int kr = n >> 4, c = n & 15;
        sgN[n4] = n;
        sgU[n4] = (unsigned)(((kr << 4) + (c ^ (kr & 15))) * 16);
    }
    const unsigned uK0 = smem_u32(dyn);
    const unsigned uV0 = uK0 + 16384;
    const unsigned uK1 = uK0 + 32768;
    const unsigned uV1 = uK0 + 49152;
    const unsigned uSk = smem_u32(sSkA);

    __syncthreads();   // sQ / sAC / sQc visible
    const float A16 = sAC[256 + wid];
    const float C16 = sAC[264 + wid];
    const float qcx = sQc[wid].x, qcy = sQc[wid].y;
    const float4* sQ4 = (const float4*)sQ;

    // prologue: stage tile 0 into buffer 0
#pragma unroll
    for (int n4 = 0; n4 < 4; ++n4) {
        cpa16(uK0 + sgU[n4], Kg + sgN[n4]);
        cpa16(uV0 + sgU[n4], Vg + sgN[n4]);
    }
    if (tid < 64) cpa8(uSk + tid*8, Skg + tid);
    asm volatile("cp.async.commit_group;");

    for (int t = 0; t < 16; ++t) {
        const int bf = t & 1;
        asm volatile("cp.async.wait_group 0;");
        __syncthreads();   // tile t visible; all warps done with tile t-1

        // restage (safe: everyone passed the barrier)
        if (t + 1 < 16) {
            const unsigned uK = bf ? uK0 : uK1;
            const unsigned uV = bf ? uV0 : uV1;
#pragma unroll
            for (int n4 = 0; n4 < 4; ++n4) {
                cpa16(uK + sgU[n4], Kg + (t+1)*1024 + sgN[n4]);
                cpa16(uV + sgU[n4], Vg + (t+1)*1024 + sgN[n4]);
            }
            if (tid < 64) cpa8(uSk + (bf ? 0u : 512u) + tid*8, Skg + (t+1)*64 + tid);
            asm volatile("cp.async.commit_group;");
        }

        // cooperative distances: warp w computes query w's row
        {
            const float2* sSk = sSkA + bf*64;
            float2 c0 = sSk[lane], c1 = sSk[lane + 32];
            float dx = qcx - c0.x, dy = qcy - c0.y;
            float d0 = fmaf(dx, dx, dy*dy);
            dx = qcx - c1.x; dy = qcy - c1.y;
            float d1 = fmaf(dx, dx, dy*dy);
            sD[wid*64 + lane]      = d0;
            sD[wid*64 + 32 + lane] = d1;
        }
        __syncthreads();   // sD ready

        const float4* sK = bf ? (dyn + 2048) : dyn;
        const float4* sV = bf ? (dyn + 3072) : (dyn + 1024);

        // s[qi*2 + kk]: scores (start from PL bias)
        float s[16];
        if (i0 == 16) {
#pragma unroll
            for (int qi = 0; qi < 8; ++qi) {
                float dq0 = sD[qi*64 + lane];
                float dq1 = sD[qi*64 + 32 + lane];
                s[qi*2+0] = fmaf(A16, dq0, C16);
                s[qi*2+1] = fmaf(A16, dq1, C16);
            }
        } else {
#pragma unroll
            for (int qi = 0; qi < 8; ++qi) {
                float dq0 = sD[qi*64 + lane];
                float dq1 = sD[qi*64 + 32 + lane];
                int m0 = i0, m1 = i0;
                for (int i = i0; i < 16; ++i) {
                    float tv = trg[i];
                    m0 += dq0 > tv; m1 += dq1 > tv;
                }
                s[qi*2+0] = fmaf(sAC[m0*16 + wid], dq0, sAC[m0*16 + 8 + wid]);
                s[qi*2+1] = fmaf(sAC[m1*16 + wid], dq1, sAC[m1*16 + 8 + wid]);
            }
        }

        // QK dots: each K load feeds 8 queries
#pragma unroll
        for (int cc = 0; cc < 2; ++cc) {
            const int ik = cc ? ikk1 : ikk0;
            float4 k0 = sK[ik];
            float4 k1 = sK[ik + 512];
#pragma unroll
            for (int qi = 0; qi < 8; ++qi) {
                float4 qv = sQ4[qi*16 + 2*wid + cc];
                s[qi*2]   = fmaf(qv.x, k0.x, s[qi*2]);
                s[qi*2]   = fmaf(qv.y, k0.y, s[qi*2]);
                s[qi*2]   = fmaf(qv.z, k0.z, s[qi*2]);
                s[qi*2]   = fmaf(qv.w, k0.w, s[qi*2]);
                s[qi*2+1] = fmaf(qv.x, k1.x, s[qi*2+1]);
                s[qi*2+1] = fmaf(qv.y, k1.y, s[qi*2+1]);
                s[qi*2+1] = fmaf(qv.z, k1.z, s[qi*2+1]);
                s[qi*2+1] = fmaf(qv.w, k1.w, s[qi*2+1]);
            }
        }

        // exp in place; accumulate l
#pragma unroll
        for (int i = 0; i < 16; ++i) s[i] = ex2f(s[i]);
#pragma unroll
        for (int qi = 0; qi < 8; ++qi) l[qi] += s[qi*2] + s[qi*2+1];

        // V accumulation: each V load feeds 8 queries
#pragma unroll
        for (int cc = 0; cc < 2; ++cc) {
            const int ik = cc ? ikk1 : ikk0;
            float4 v0 = sV[ik];
            float4 v1 = sV[ik + 512];
#pragma unroll
            for (int qi = 0; qi < 8; ++qi) {
                const int ob = qi*8 + cc*4;
                float pa = s[qi*2], pb = s[qi*2+1];
                o[ob+0] = fmaf(pa, v0.x, o[ob+0]);
                o[ob+0] = fmaf(pb, v1.x, o[ob+0]);
                o[ob+1] = fmaf(pa, v0.y, o[ob+1]);
                o[ob+1] = fmaf(pb, v1.y, o[ob+1]);
                o[ob+2] = fmaf(pa, v0.z, o[ob+2]);
                o[ob+2] = fmaf(pb, v1.z, o[ob+2]);
                o[ob+3] = fmaf(pa, v0.w, o[ob+3]);
                o[ob+3] = fmaf(pb, v1.w, o[ob+3]);
            }
        }
    }

    // merge lanes (butterfly)
#pragma unroll
    for (int i = 0; i < 8; ++i) {
        float lh = l[i];
#pragma unroll
        for (int off = 16; off; off >>= 1)
            lh += __shfl_xor_sync(0xffffffffu, lh, off);
        l[i] = 1.f / lh;
    }
#pragma unroll
    for (int d = 0; d < 64; ++d) {
        float v = o[d];
#pragma unroll
        for (int off = 16; off; off >>= 1)
            v += __shfl_xor_sync(0xffffffffu, v, off);
        o[d] = v * l[d >> 3];
    }

    // lane i extracts o[i], o[32+i]
    float mv0 = 0.f, mv1 = 0.f;
#pragma unroll
    for (int i = 0; i < 32; ++i)
        if (lane == i) { mv0 = o[i]; mv1 = o[32 + i]; }

    __syncthreads();   // all warps done with last tile K/V before Wo staging
    sO[(lane >> 3)*64     + wid*8 + (lane & 7)] = mv0;
    sO[(4 + (lane >> 3))*64 + wid*8 + (lane & 7)] = mv1;
    float* sWo = (float*)dyn;
    const float* Wog = wo + iblk*4096;
    for (int n = tid; n < 4096; n += 256) sWo[n] = Wog[n];
    __syncthreads();

    // out-proj + residual + LN: queries qA = tid>>6 and qB = qA+4
    const int c = tid & 63, qA = tid >> 6, qB = qA + 4;
    const int rowA = b*LL + blockIdx.x*8 + qA;
    const int rowB = rowA + 4;
    float accA = bo[iblk*64 + c], accB = accA;
#pragma unroll 16
    for (int i = 0; i < 64; ++i) {
        float w = sWo[i*64 + c];
        accA = fmaf(sO[qA*64 + i], w, accA);
        accB = fmaf(sO[qB*64 + i], w, accB);
    }
    const float* src = side ? g_kvs : g_qvs;
    accA += src[rowA*64 + c];
    accB += src[rowB*64 + c];

    float s1A = accA, s2A = accA*accA, s1B = accB, s2B = accB*accB;
#pragma unroll
    for (int off = 16; off; off >>= 1) {
        s1A += __shfl_xor_sync(0xffffffffu, s1A, off);
        s2A += __shfl_xor_sync(0xffffffffu, s2A, off);
        s1B += __shfl_xor_sync(0xffffffffu, s1B, off);
        s2B += __shfl_xor_sync(0xffffffffu, s2B, off);
    }
    const int half = (tid >> 5) & 1;
    if (lane == 0) {
        sRed[qA][half][0] = s1A; sRed[qA][half][1] = s2A;
        sRed[qB][half][0] = s1B; sRed[qB][half][1] = s2B;
    }
    __syncthreads();
    float* outp = side ? g_attk : g_attq;
    const float nsv = ns[iblk*64 + c], nbv = nb[iblk*64 + c];
    {
        float tot  = sRed[qA][0][0] + sRed[qA][1][0];
        float tot2 = sRed[qA][0][1] + sRed[qA][1][1];
        float mu = tot * (1.f/64.f);
        float var = tot2 * (1.f/64.f) - mu*mu;
        float rstd = rsqrtf(var + 1e-6f);
        outp[rowA*64 + c] = (accA - mu) * rstd * nsv + nbv;
    }
    {
        float tot  = sRed[qB][0][0] + sRed[qB][1][0];
        float tot2 = sRed[qB][0][1] + sRed[qB][1][1];
        float mu = tot * (1.f/64.f);
        float var = tot2 * (1.f/64.f) - mu*mu;
        float rstd = rsqrtf(var + 1e-6f);
        outp[rowB*64 + c] = (accB - mu) * rstd * nsv + nbv;
    }
}

// ---------------------------------------------------------------------------
// FFN + residual + LN + next-block projections.
// W1/W2 cp.async-staged into 64KB dynamic smem (once per CTA, overlapped).
// ---------------------------------------------------------------------------
__global__ __launch_bounds__(128) void ffnproj_kernel(
    int iblk, int nblk,
    const float* __restrict__ fw1, const float* __restrict__ fb1,
    const float* __restrict__ fw2, const float* __restrict__ fb2,
    const float* __restrict__ ns, const float* __restrict__ nb,
    const float* __restrict__ wq, const float* __restrict__ bq,
    const float* __restrict__ wk, const float* __restrict__ bk,
    const float* __restrict__ wv, const float* __restrict__ bv)
{
    extern __shared__ float wsm[];   // [0..8191] W1, [8192..16383] W2
    __shared__ float sx[8][64];
    __shared__ float sh[8][128];
    __shared__ float sy[8][64];
    __shared__ float sred[8][2][2];

    int tid = threadIdx.x;
    int row0 = blockIdx.x * 8;
    int side = row0 >> 11;
    int r0 = row0 & 2047;
    const float* src = side ? g_attk : g_attq;
    float* dst = side ? g_kvs : g_qvs;

    // stage weights (async)
    {
        const float* W1g = fw1 + iblk*8192;
        const float* W2g = fw2 + iblk*8192;
        unsigned uw = smem_u32(wsm);
#pragma unroll
        for (int n = 0; n < 16; ++n) {
            int idx = n*512 + tid*4;
            cpa16(uw + idx*4, W1g + idx);
            cpa16(uw + 32768 + idx*4, W2g + idx);
        }
        asm volatile("cp.async.commit_group;");
    }
    for (int n = tid; n < 512; n += 128) sx[n >> 6][n & 63] = src[r0*64 + n];
    asm volatile("cp.async.wait_group 0;");
    __syncthreads();

    float b1v = fb1[iblk*128 + tid];
    float acc[8];
#pragma unroll
    for (int r = 0; r < 8; ++r) acc[r] = b1v;
#pragma unroll 16
    for (int k = 0; k < 64; ++k) {
        float w = wsm[k*128 + tid];
#pragma unroll
        for (int r = 0; r < 8; ++r) acc[r] = fmaf(sx[r][k], w, acc[r]);
    }
#pragma unroll
    for (int r = 0; r < 8; ++r) sh[r][tid] = fmaxf(acc[r], 0.f);
    __syncthreads();

    const float* W2s = wsm + 8192;
    int c = tid & 63, g = tid >> 6;
    float b2v = fb2[iblk*64 + c];
    float a2[4];
#pragma unroll
    for (int r = 0; r < 4; ++r) a2[r] = b2v;
#pragma unroll 16
    for (int k = 0; k < 128; ++k) {
        float w = W2s[k*64 + c];
#pragma unroll
        for (int r = 0; r < 4; ++r) a2[r] = fmaf(sh[g*4 + r][k], w, a2[r]);
    }
#pragma unroll
    for (int r = 0; r < 4; ++r) a2[r] += sx[g*4 + r][c];

    float s1[4], s2[4];
#pragma unroll
    for (int r = 0; r < 4; ++r) { s1[r] = a2[r]; s2[r] = a2[r]*a2[r]; }
#pragma unroll
    for (int off = 16; off; off >>= 1) {
#pragma unroll
        for (int r = 0; r < 4; ++r) {
            s1[r] += __shfl_xor_sync(0xffffffffu, s1[r], off);
            s2[r] += __shfl_xor_sync(0xffffffffu, s2[r], off);
        }
    }
    int lane = tid & 31, half = (tid >> 5) & 1;
    if (lane == 0) {
#pragma unroll
        for (int r = 0; r < 4; ++r) {
            sred[g*4 + r][half][0] = s1[r];
            sred[g*4 + r][half][1] = s2[r];
        }
    }
    __syncthreads();
    float nsv = ns[iblk*64 + c], nbv = nb[iblk*64 + c];
#pragma unroll
    for (int r = 0; r < 4; ++r) {
        int rr = g*4 + r;
        float tot  = sred[rr][0][0] + sred[rr][1][0];
        float tot2 = sred[rr][0][1] + sred[rr][1][1];
        float mu = tot * (1.f/64.f);
        float var = tot2 * (1.f/64.f) - mu*mu;
        float rstd = rsqrtf(var + 1e-6f);
        float y = (a2[r] - mu) * rstd * nsv + nbv;
        sy[rr][c] = y;
        dst[(r0 + rr)*64 + c] = y;
    }
    __syncthreads();

    if (nblk < 0) return;

    const float* Wm[3]; const float* Bm[3]; float* Dm[3]; int nmat;
    if (side == 0) {
        nmat = 1;
        Wm[0] = wq + nblk*4096; Bm[0] = bq + nblk*64; Dm[0] = g_q1;
    } else {
        nmat = 3;
        Wm[0] = wq + nblk*4096; Bm[0] = bq + nblk*64; Dm[0] = g_q2;
        Wm[1] = wk + nblk*4096; Bm[1] = bk + nblk*64; Dm[1] = g_kk;
        Wm[2] = wv + nblk*4096; Bm[2] = bv + nblk*64; Dm[2] = g_vv;
    }
    for (int mm = 0; mm < nmat; ++mm) {
        const float* W = Wm[mm];
        float bv = Bm[mm][c];
        float pa[4];
#pragma unroll
        for (int r = 0; r < 4; ++r) pa[r] = bv;
#pragma unroll 16
        for (int k = 0; k < 64; ++k) {
            float w = W[k*64 + c];
#pragma unroll
            for (int r = 0; r < 4; ++r) pa[r] = fmaf(sy[g*4 + r][k], w, pa[r]);
        }
#pragma unroll
        for (int r = 0; r < 4; ++r) Dm[mm][(r0 + g*4 + r)*64 + c] = pa[r];
    }
}

// ---------------------------------------------------------------------------
// Head
// ---------------------------------------------------------------------------
__global__ __launch_bounds__(128) void head_kernel(
    const float* __restrict__ fns, const float* __restrict__ fnb,
    const float* __restrict__ hw1, const float* __restrict__ hb1,
    const float* __restrict__ hw2, const float* __restrict__ hb2,
    float* __restrict__ out)
{
    __shared__ float sx[64], sh[128], sp0[128], sp1[128], sred[2];
    int row = blockIdx.x, tid = threadIdx.x;
    if (tid < 64) sx[tid] = g_qvs[row*64 + tid];
    __syncthreads();
    if (tid < 32) {
        float v0 = sx[tid], v1 = sx[tid + 32];
        float s = v0 + v1;
#pragma unroll
        for (int off = 16; off; off >>= 1)
            s += __shfl_xor_sync(0xffffffffu, s, off);
        float mu = s * (1.f/64.f);
        float e0 = v0 - mu, e1 = v1 - mu;
        float qv = fmaf(e0, e0, e1*e1);
#pragma unroll
        for (int off = 16; off; off >>= 1)
            qv += __shfl_xor_sync(0xffffffffu, qv, off);
        if (tid == 0) { sred[0] = mu; sred[1] = rsqrtf(qv*(1.f/64.f) + 1e-6f); }
    }
    __syncthreads();
    if (tid < 64) sx[tid] = (sx[tid] - sred[0]) * sred[1] * fns[tid] + fnb[tid];
    __syncthreads();
    float acc = hb1[tid];
#pragma unroll 16
    for (int k = 0; k < 64; ++k) acc = fmaf(sx[k], hw1[k*128 + tid], acc);
    sh[tid] = fmaxf(acc, 0.f);
    __syncthreads();
    sp0[tid] = sh[tid] * hw2[tid*2 + 0];
    sp1[tid] = sh[tid] * hw2[tid*2 + 1];
    __syncthreads();
    for (int s = 64; s > 0; s >>= 1) {
        if (tid < s) { sp0[tid] += sp0[tid + s]; sp1[tid] += sp1[tid + s]; }
        __syncthreads();
    }
    if (tid == 0) {
        out[row]        = sp0[0] + hb2[0];
        out[2048 + row] = __expf(0.5f * (sp1[0] + hb2[1]));
    }
}

// ---------------------------------------------------------------------------
extern "C" void kernel_launch(void* const* d_in, const int* in_sizes, int n_in,
                              void* d_out, int out_size)
{
    const float* s_ctx   = (const float*)d_in[0];
    const float* f_ctx   = (const float*)d_in[1];
    const float* s_test  = (const float*)d_in[2];
    const float* table   = (const float*)d_in[3];
    const float* emb_w1  = (const float*)d_in[4];
    const float* emb_b1  = (const float*)d_in[5];
    const float* emb_w2  = (const float*)d_in[6];
    const float* emb_b2  = (const float*)d_in[7];
    const float* attn_wq = (const float*)d_in[8];
    const float* attn_bq = (const float*)d_in[9];
    const float* attn_wk = (const float*)d_in[10];
    const float* attn_bk = (const float*)d_in[11];
    const float* attn_wv = (const float*)d_in[12];
    const float* attn_bv = (const float*)d_in[13];
    const float* attn_wo = (const float*)d_in[14];
    const float* attn_bo = (const float*)d_in[15];
    const float* ffn_w1  = (const float*)d_in[16];
    const float* ffn_b1  = (const float*)d_in[17];
    const float* ffn_w2  = (const float*)d_in[18];
    const float* ffn_b2  = (const float*)d_in[19];
    const float* bias_w1 = (const float*)d_in[20];
    const float* bias_b1 = (const float*)d_in[21];
    const float* bias_w2 = (const float*)d_in[22];
    const float* bias_b2 = (const float*)d_in[23];
    const float* norm_s  = (const float*)d_in[24];
    const float* norm_b  = (const float*)d_in[25];
    const float* fnorm_s = (const float*)d_in[26];
    const float* fnorm_b = (const float*)d_in[27];
    const float* head_w1 = (const float*)d_in[28];
    const float* head_b1 = (const float*)d_in[29];
    const float* head_w2 = (const float*)d_in[30];
    const float* head_b2 = (const float*)d_in[31];

    static int attr_done = 0;
    if (!attr_done) {
        cudaFuncSetAttribute(attn_kernel,
            cudaFuncAttributeMaxDynamicSharedMemorySize, 65536);
        cudaFuncSetAttribute(ffnproj_kernel,
            cudaFuncAttributeMaxDynamicSharedMemorySize, 65536);
        attr_done = 1;
    }

    bias_setup_kernel<<<6, 32>>>(bias_w1, bias_b1, bias_w2, bias_b2);
    embed_kernel<<<1024, 256>>>(s_ctx, f_ctx, s_test, table,
                                emb_w1, emb_b1, emb_w2, emb_b2);
    proj_kernel<<<dim3(64, 4), 256>>>(0, attn_wq, attn_bq,
                                      attn_wk, attn_bk, attn_wv, attn_bv);
    for (int i = 0; i < 6; ++i) {
        attn_kernel<<<dim3(128, BB, 2), 256, 65536>>>(i, s_test, s_ctx,
                                                      attn_wo, attn_bo,
                                                      norm_s, norm_b);
        ffnproj_kernel<<<512, 128, 65536>>>(i, (i < 5) ? i + 1 : -1,
                                            ffn_w1, ffn_b1, ffn_w2, ffn_b2,
                                            norm_s, norm_b,
                                            attn_wq, attn_bq, attn_wk, attn_bk,
                                            attn_wv, attn_bv);
    }
    head_kernel<<<2048, 128>>>(fnorm_s, fnorm_b, head_w1, head_b1,
                               head_w2, head_b2, (float*)d_out);
}